// round 6
// baseline (speedup 1.0000x reference)
#include <cuda_runtime.h>
#include <cuda_bf16.h>
#include <cstdint>

#define DEV_INLINE __device__ __forceinline__

constexpr int B_   = 4;
constexpr int K_   = 2048;
constexpr int P_   = 4096;
constexpr int NB   = 16;
constexpr int CIN  = 64;
constexpr int CMID = 32;
constexpr int FH   = 256;
constexpr int COUT = 128;
constexpr int GK   = B_ * K_;        // 8192 keys total
constexpr int EDIM = CMID * CIN;     // 2048

// Scratch (allocation-free rule: __device__ globals)
__device__ int            g_idx[GK * NB];
__device__ __nv_bfloat16  g_Ehi[(size_t)GK * EDIM];   // 32 MB
__device__ __nv_bfloat16  g_Elo[(size_t)GK * EDIM];   // 32 MB
__device__ __nv_bfloat16  g_Whi[(size_t)FH * EDIM];   // W0^T split, [256][2048]
__device__ __nv_bfloat16  g_Wlo[(size_t)FH * EDIM];
__device__ float          g_H[(size_t)GK * FH];       // 8 MB

// ---------------------------------------------------------------------------
// PTX helpers (cp.async / ldmatrix / mma.sync — all baseline sm_80+ ops,
// compile for plain .target sm_103; no arch-'a' accelerated features)
// ---------------------------------------------------------------------------
DEV_INLINE uint32_t smem_u32(const void* p) {
    return (uint32_t)__cvta_generic_to_shared(p);
}

DEV_INLINE void cp_async16(uint32_t dst, const void* src) {
    asm volatile("cp.async.cg.shared.global [%0], [%1], 16;"
                 :: "r"(dst), "l"(src) : "memory");
}
DEV_INLINE void cp_commit()  { asm volatile("cp.async.commit_group;" ::: "memory"); }
template <int N> DEV_INLINE void cp_wait() {
    asm volatile("cp.async.wait_group %0;" :: "n"(N) : "memory");
}

DEV_INLINE void ldm_x4(uint32_t* r, uint32_t addr) {
    asm volatile("ldmatrix.sync.aligned.m8n8.x4.shared.b16 {%0,%1,%2,%3}, [%4];"
                 : "=r"(r[0]), "=r"(r[1]), "=r"(r[2]), "=r"(r[3]) : "r"(addr));
}

DEV_INLINE void mma_bf16(float* d, const uint32_t* a, uint32_t b0, uint32_t b1) {
    asm volatile(
        "mma.sync.aligned.m16n8k16.row.col.f32.bf16.bf16.f32 "
        "{%0,%1,%2,%3}, {%4,%5,%6,%7}, {%8,%9}, {%0,%1,%2,%3};"
        : "+f"(d[0]), "+f"(d[1]), "+f"(d[2]), "+f"(d[3])
        : "r"(a[0]), "r"(a[1]), "r"(a[2]), "r"(a[3]), "r"(b0), "r"(b1));
}

// ---------------------------------------------------------------------------
// Kernel 1: KNN — 1 warp per key (verified round 1)
// ---------------------------------------------------------------------------
__global__ void __launch_bounds__(256) knn_kernel(
    const float* __restrict__ keys, const float* __restrict__ points)
{
    __shared__ float sp[P_ * 3];
    const int warp = threadIdx.x >> 5;
    const int lane = threadIdx.x & 31;
    const int g = blockIdx.x * 8 + warp;
    const int b = g >> 11;

    const float* pb = points + (size_t)b * P_ * 3;
    for (int i = threadIdx.x; i < P_ * 3; i += 256) sp[i] = pb[i];
    __syncthreads();

    const float kx = keys[g * 3 + 0];
    const float ky = keys[g * 3 + 1];
    const float kz = keys[g * 3 + 2];

    float bd[NB]; int bi[NB];
#pragma unroll
    for (int j = 0; j < NB; ++j) { bd[j] = 3.4e38f; bi[j] = 0x7fffffff; }

    for (int p = lane; p < P_; p += 32) {
        float dx = __fsub_rn(sp[p * 3 + 0], kx);
        float dy = __fsub_rn(sp[p * 3 + 1], ky);
        float dz = __fsub_rn(sp[p * 3 + 2], kz);
        float d  = __fadd_rn(__fadd_rn(__fmul_rn(dx, dx), __fmul_rn(dy, dy)),
                             __fmul_rn(dz, dz));
        if (d < bd[NB - 1]) {
            float cd = d; int ci = p;
#pragma unroll
            for (int j = 0; j < NB; ++j) {
                bool  sw = (cd < bd[j]);
                float tf = sw ? bd[j] : cd;
                int   ti = sw ? bi[j] : ci;
                bd[j] = sw ? cd : bd[j];
                bi[j] = sw ? ci : bi[j];
                cd = tf; ci = ti;
            }
        }
    }

    int res_i = 0;
    for (int t = 0; t < NB; ++t) {
        float vd = bd[0]; int vi = bi[0]; int vl = lane;
#pragma unroll
        for (int off = 16; off > 0; off >>= 1) {
            float od = __shfl_xor_sync(0xffffffffu, vd, off);
            int   oi = __shfl_xor_sync(0xffffffffu, vi, off);
            int   ol = __shfl_xor_sync(0xffffffffu, vl, off);
            if (od < vd || (od == vd && oi < vi)) { vd = od; vi = oi; vl = ol; }
        }
        if (lane == t) res_i = vi;
        if (lane == vl) {
#pragma unroll
            for (int j = 0; j < NB - 1; ++j) { bd[j] = bd[j + 1]; bi[j] = bi[j + 1]; }
            bd[NB - 1] = 3.4e38f; bi[NB - 1] = 0x7fffffff;
        }
    }
    if (lane < NB) g_idx[g * NB + lane] = res_i;
}

// ---------------------------------------------------------------------------
// Kernel 2: per-edge weight MLP + aggregation, emits bf16 hi/lo E (verified)
// ---------------------------------------------------------------------------
__global__ void __launch_bounds__(128) edge_kernel(
    const float* __restrict__ keys, const float* __restrict__ points,
    const float* __restrict__ feats,
    const float* __restrict__ w0, const float* __restrict__ b0,
    const float* __restrict__ w1, const float* __restrict__ b1,
    const float* __restrict__ w2, const float* __restrict__ b2)
{
    __shared__ __align__(16) float sw0[3][32];
    __shared__ float sb0[32], sb1[32], sb2[32];
    __shared__ __align__(16) float sw1t[32][32];
    __shared__ __align__(16) float sw2t[32][32];
    __shared__ __align__(16) float sm_m[4][NB][32];
    __shared__ __align__(16) float sm_f[4][NB][CIN];

    const int t = threadIdx.x;
    const int w = t >> 5, lane = t & 31;

    for (int i = t; i < 96; i += 128) sw0[i / 32][i % 32] = w0[i];
    if (t < 32) { sb0[t] = b0[t]; sb1[t] = b1[t]; sb2[t] = b2[t]; }
    for (int i = t; i < 1024; i += 128) {
        sw1t[i % 32][i / 32] = w1[i];
        sw2t[i % 32][i / 32] = w2[i];
    }
    __syncthreads();

    const int g = blockIdx.x * 4 + w;
    const int b = g >> 11;

    if (lane < NB) {
        const int n  = lane;
        const int gi = g_idx[g * NB + n];
        const float rx = points[((size_t)b * P_ + gi) * 3 + 0] - keys[g * 3 + 0];
        const float ry = points[((size_t)b * P_ + gi) * 3 + 1] - keys[g * 3 + 1];
        const float rz = points[((size_t)b * P_ + gi) * 3 + 2] - keys[g * 3 + 2];

        float h1[32];
#pragma unroll
        for (int j = 0; j < 32; ++j)
            h1[j] = fmaxf(fmaf(rx, sw0[0][j], fmaf(ry, sw0[1][j],
                          fmaf(rz, sw0[2][j], sb0[j]))), 0.0f);

        float h2[32];
#pragma unroll
        for (int j = 0; j < 32; ++j) {
            float a = sb1[j];
            const float4* wr = (const float4*)sw1t[j];
#pragma unroll
            for (int q = 0; q < 8; ++q) {
                float4 wv = wr[q];
                a = fmaf(h1[4 * q + 0], wv.x, a);
                a = fmaf(h1[4 * q + 1], wv.y, a);
                a = fmaf(h1[4 * q + 2], wv.z, a);
                a = fmaf(h1[4 * q + 3], wv.w, a);
            }
            h2[j] = fmaxf(a, 0.0f);
        }
#pragma unroll
        for (int j = 0; j < 32; ++j) {
            float a = sb2[j];
            const float4* wr = (const float4*)sw2t[j];
#pragma unroll
            for (int q = 0; q < 8; ++q) {
                float4 wv = wr[q];
                a = fmaf(h2[4 * q + 0], wv.x, a);
                a = fmaf(h2[4 * q + 1], wv.y, a);
                a = fmaf(h2[4 * q + 2], wv.z, a);
                a = fmaf(h2[4 * q + 3], wv.w, a);
            }
            sm_m[w][n][j] = a;
        }
    } else {
        const int n  = lane - NB;
        const int gi = g_idx[g * NB + n];
        const float4* src = (const float4*)(feats + ((size_t)b * P_ + gi) * CIN);
        float4* dst = (float4*)sm_f[w][n];
#pragma unroll
        for (int i = 0; i < CIN / 4; ++i) dst[i] = src[i];
    }
    __syncwarp();

    float e0[32], e1[32];
#pragma unroll
    for (int j = 0; j < 32; ++j) { e0[j] = 0.0f; e1[j] = 0.0f; }

#pragma unroll
    for (int n = 0; n < NB; ++n) {
        const float f0 = sm_f[w][n][lane];
        const float f1 = sm_f[w][n][lane + 32];
        const float4* mp = (const float4*)sm_m[w][n];
#pragma unroll
        for (int q = 0; q < 8; ++q) {
            float4 mv = mp[q];
            e0[4 * q + 0] = fmaf(mv.x, f0, e0[4 * q + 0]);
            e1[4 * q + 0] = fmaf(mv.x, f1, e1[4 * q + 0]);
            e0[4 * q + 1] = fmaf(mv.y, f0, e0[4 * q + 1]);
            e1[4 * q + 1] = fmaf(mv.y, f1, e1[4 * q + 1]);
            e0[4 * q + 2] = fmaf(mv.z, f0, e0[4 * q + 2]);
            e1[4 * q + 2] = fmaf(mv.z, f1, e1[4 * q + 2]);
            e0[4 * q + 3] = fmaf(mv.w, f0, e0[4 * q + 3]);
            e1[4 * q + 3] = fmaf(mv.w, f1, e1[4 * q + 3]);
        }
    }

    __nv_bfloat16* Eh = g_Ehi + (size_t)g * EDIM;
    __nv_bfloat16* El = g_Elo + (size_t)g * EDIM;
#pragma unroll
    for (int mc = 0; mc < 32; ++mc) {
        float v0 = e0[mc];
        __nv_bfloat16 h0 = __float2bfloat16(v0);
        Eh[mc * 64 + lane] = h0;
        El[mc * 64 + lane] = __float2bfloat16(v0 - __bfloat162float(h0));
        float v1 = e1[mc];
        __nv_bfloat16 h1b = __float2bfloat16(v1);
        Eh[mc * 64 + 32 + lane] = h1b;
        El[mc * 64 + 32 + lane] = __float2bfloat16(v1 - __bfloat162float(h1b));
    }
}

// ---------------------------------------------------------------------------
// Kernel 3: split + transpose W0 [2048,256] fp32 -> W0^T hi/lo [256][2048] bf16
// ---------------------------------------------------------------------------
__global__ void __launch_bounds__(256) convw_kernel(const float* __restrict__ W)
{
    int idx = blockIdx.x * 256 + threadIdx.x;
    int n = idx >> 11;
    int k = idx & 2047;
    float v = W[(size_t)k * FH + n];
    __nv_bfloat16 h = __float2bfloat16(v);
    g_Whi[idx] = h;
    g_Wlo[idx] = __float2bfloat16(v - __bfloat162float(h));
}

// ---------------------------------------------------------------------------
// Kernel 4: gemm1 via mma.sync (HMMA bf16, fp32 acc), 3-term error split.
// H = relu(E @ W0 + b0). Tile 128x128, BK=64, SW128 smem, 2-stage cp.async.
// 8 warps in 2x4; warp tile 64x32.
// ---------------------------------------------------------------------------
constexpr int G1_STAGE = 4 * 16384;          // Ahi, Alo, Bhi, Blo
constexpr int G1_SMEM  = 2 * G1_STAGE;       // 131072
constexpr int G1_NI    = EDIM / 64;          // 32 K-chunks

__global__ void __launch_bounds__(256, 1) gemm1_mma_kernel(const float* __restrict__ bias)
{
    extern __shared__ char smem[];
    const uint32_t base = smem_u32(smem);
    const int tid  = threadIdx.x;
    const int wid  = tid >> 5;
    const int lane = tid & 31;
    const int m0 = blockIdx.y * 128;
    const int n0 = blockIdx.x * 128;
    const int warpM = (wid & 1) * 64;
    const int warpN = (wid >> 1) * 32;

    const __nv_bfloat16* srcA_hi = g_Ehi + (size_t)m0 * EDIM;
    const __nv_bfloat16* srcA_lo = g_Elo + (size_t)m0 * EDIM;
    const __nv_bfloat16* srcB_hi = g_Whi + (size_t)n0 * EDIM;
    const __nv_bfloat16* srcB_lo = g_Wlo + (size_t)n0 * EDIM;

    auto load_stage = [&](int it) {
        const uint32_t sb = base + (it & 1) * G1_STAGE;
        const int k0 = it * 64;
        const __nv_bfloat16* srcs[4] = {srcA_hi, srcA_lo, srcB_hi, srcB_lo};
#pragma unroll
        for (int sub = 0; sub < 4; ++sub) {
            const __nv_bfloat16* sp = srcs[sub] + k0;
            const uint32_t sbase = sb + sub * 16384;
#pragma unroll
            for (int j = 0; j < 4; ++j) {
                const int idx = tid + j * 256;              // 0..1023
                const int r = idx >> 3, c = idx & 7;
                const uint32_t off = (uint32_t)idx * 16;
                const uint32_t dst = sbase + (off ^ ((off >> 3) & 0x70));
                cp_async16(dst, sp + (size_t)r * EDIM + c * 8);
            }
        }
    };

    float acc[4][4][4];
#pragma unroll
    for (int i = 0; i < 4; ++i)
#pragma unroll
        for (int j = 0; j < 4; ++j)
#pragma unroll
            for (int q = 0; q < 4; ++q) acc[i][j][q] = 0.0f;

    // Per-lane ldmatrix row/col components (within a 16x16 tile of [128][64] smem)
    const int aRow = ((lane >> 3) & 1) * 8 + (lane & 7);   // row within tile
    const int aKof = (lane >> 4) * 8;                      // k-half
    const int bRow = ((lane >> 4) & 1) * 8 + (lane & 7);   // n within n16 tile
    const int bKof = ((lane >> 3) & 1) * 8;                // k-half

    load_stage(0);
    cp_commit();

    for (int it = 0; it < G1_NI; ++it) {
        if (it + 1 < G1_NI) {
            load_stage(it + 1);
            cp_commit();
            cp_wait<1>();
        } else {
            cp_wait<0>();
        }
        __syncthreads();

        const uint32_t sb = base + (it & 1) * G1_STAGE;
        const uint32_t sA_hi = sb;
        const uint32_t sA_lo = sb + 16384;
        const uint32_t sB_hi = sb + 32768;
        const uint32_t sB_lo = sb + 49152;

#pragma unroll
        for (int kk = 0; kk < 4; ++kk) {
            const int k0 = kk * 16;
            uint32_t ah[4][4], al[4][4], bh[2][4], bl[2][4];
#pragma unroll
            for (int mi = 0; mi < 4; ++mi) {
                const int row = warpM + mi * 16 + aRow;
                const int col = k0 + aKof;
                const uint32_t off = (uint32_t)(row * 128 + col * 2);
                const uint32_t sw  = off ^ ((off >> 3) & 0x70);
                ldm_x4(ah[mi], sA_hi + sw);
                ldm_x4(al[mi], sA_lo + sw);
            }
#pragma unroll
            for (int nj = 0; nj < 2; ++nj) {
                const int row = warpN + nj * 16 + bRow;
                const int col = k0 + bKof;
                const uint32_t off = (uint32_t)(row * 128 + col * 2);
                const uint32_t sw  = off ^ ((off >> 3) & 0x70);
                ldm_x4(bh[nj], sB_hi + sw);
                ldm_x4(bl[nj], sB_lo + sw);
            }
#pragma unroll
            for (int mi = 0; mi < 4; ++mi)
#pragma unroll
                for (int nj = 0; nj < 2; ++nj)
#pragma unroll
                    for (int nk = 0; nk < 2; ++nk) {
                        float* d = acc[mi][nj * 2 + nk];
                        mma_bf16(d, ah[mi], bh[nj][nk * 2], bh[nj][nk * 2 + 1]);
                        mma_bf16(d, ah[mi], bl[nj][nk * 2], bl[nj][nk * 2 + 1]);
                        mma_bf16(d, al[mi], bh[nj][nk * 2], bh[nj][nk * 2 + 1]);
                    }
        }
        __syncthreads();
    }

    // Epilogue: bias + relu, fp32 out. c-frag: (row = lane>>2 [+8], col = 2*(lane&3))
#pragma unroll
    for (int mi = 0; mi < 4; ++mi) {
        const int row = m0 + warpM + mi * 16 + (lane >> 2);
#pragma unroll
        for (int ni = 0; ni < 4; ++ni) {
            const int col = n0 + warpN + ni * 8 + 2 * (lane & 3);
            const float b0v = bias[col], b1v = bias[col + 1];
            float2 v0, v1;
            v0.x = fmaxf(acc[mi][ni][0] + b0v, 0.0f);
            v0.y = fmaxf(acc[mi][ni][1] + b1v, 0.0f);
            v1.x = fmaxf(acc[mi][ni][2] + b0v, 0.0f);
            v1.y = fmaxf(acc[mi][ni][3] + b1v, 0.0f);
            *(float2*)&g_H[(size_t)row * FH + col]       = v0;
            *(float2*)&g_H[(size_t)(row + 8) * FH + col] = v1;
        }
    }
}

// ---------------------------------------------------------------------------
// gemm2: fp32 FFMA2 tiled GEMM — C = H @ W1 + b1
// ---------------------------------------------------------------------------
template <int BM, int BN, int BK, int TM, int TN, bool RELU>
DEV_INLINE void gemm_body(const float* __restrict__ A, const float* __restrict__ Bw,
                          const float* __restrict__ bias, float* __restrict__ C,
                          int M, int N, int Kd)
{
    constexpr int THREADS = (BM / TM) * (BN / TN);
    constexpr int LDA = BM + 4;
    __shared__ __align__(16) float As[BK][LDA];
    __shared__ __align__(16) float Bs[BK][BN];

    const int t  = threadIdx.x;
    const int tx = t % (BN / TN);
    const int ty = t / (BN / TN);
    const int m0 = blockIdx.y * BM;
    const int n0 = blockIdx.x * BN;

    constexpr int AV = (BM * BK / 4) / THREADS;
    constexpr int BV = (BK * BN / 4) / THREADS;

    float4 aR[AV], bR[BV];
    int aRow[AV], aCol[AV], bRow[BV], bCol[BV];
#pragma unroll
    for (int i = 0; i < AV; ++i) {
        int id = t + i * THREADS; aRow[i] = id / (BK / 4); aCol[i] = id % (BK / 4);
    }
#pragma unroll
    for (int i = 0; i < BV; ++i) {
        int id = t + i * THREADS; bRow[i] = id / (BN / 4); bCol[i] = id % (BN / 4);
    }

    auto gload = [&](int k0) {
#pragma unroll
        for (int i = 0; i < AV; ++i)
            aR[i] = *(const float4*)&A[(size_t)(m0 + aRow[i]) * Kd + k0 + aCol[i] * 4];
#pragma unroll
        for (int i = 0; i < BV; ++i)
            bR[i] = *(const float4*)&Bw[(size_t)(k0 + bRow[i]) * N + n0 + bCol[i] * 4];
    };
    auto sstore = [&]() {
#pragma unroll
        for (int i = 0; i < AV; ++i) {
            As[aCol[i] * 4 + 0][aRow[i]] = aR[i].x;
            As[aCol[i] * 4 + 1][aRow[i]] = aR[i].y;
            As[aCol[i] * 4 + 2][aRow[i]] = aR[i].z;
            As[aCol[i] * 4 + 3][aRow[i]] = aR[i].w;
        }
#pragma unroll
        for (int i = 0; i < BV; ++i)
            *(float4*)&Bs[bRow[i]][bCol[i] * 4] = bR[i];
    };

    unsigned long long acc[TM][TN / 2];
#pragma unroll
    for (int i = 0; i < TM; ++i)
#pragma unroll
        for (int j = 0; j < TN / 2; ++j) acc[i][j] = 0ull;

    auto compute = [&]() {
#pragma unroll
        for (int k = 0; k < BK; ++k) {
            float aF[TM];
#pragma unroll
            for (int v = 0; v < TM / 4; ++v) {
                float4 tmp = *(const float4*)&As[k][ty * TM + v * 4];
                aF[v * 4 + 0] = tmp.x; aF[v * 4 + 1] = tmp.y;
                aF[v * 4 + 2] = tmp.z; aF[v * 4 + 3] = tmp.w;
            }
            unsigned long long bP[TN / 2];
#pragma unroll
            for (int v = 0; v < TN / 4; ++v) {
                ulonglong2 tmp = *(const ulonglong2*)&Bs[k][tx * TN + v * 4];
                bP[v * 2] = tmp.x; bP[v * 2 + 1] = tmp.y;
            }
#pragma unroll
            for (int i = 0; i < TM; ++i) {
                unsigned long long aa;
                asm("mov.b64 %0, {%1, %1};" : "=l"(aa) : "r"(__float_as_uint(aF[i])));
#pragma unroll
                for (int j = 0; j < TN / 2; ++j)
                    asm("fma.rn.f32x2 %0, %1, %2, %0;"
                        : "+l"(acc[i][j]) : "l"(aa), "l"(bP[j]));
            }
        }
    };

    gload(0);
    sstore();
    __syncthreads();
    for (int k0 = BK; k0 < Kd; k0 += BK) {
        gload(k0);
        compute();
        __syncthreads();
        sstore();
        __syncthreads();
    }
    compute();

    float bia[TN];
#pragma unroll
    for (int j = 0; j < TN; ++j) bia[j] = bias[n0 + tx * TN + j];
#pragma unroll
    for (int i = 0; i < TM; ++i) {
        float outv[TN];
#pragma unroll
        for (int j = 0; j < TN / 2; ++j) {
            float lo = __uint_as_float((unsigned)(acc[i][j] & 0xffffffffull));
            float hi = __uint_as_float((unsigned)(acc[i][j] >> 32));
            outv[2 * j]     = lo + bia[2 * j];
            outv[2 * j + 1] = hi + bia[2 * j + 1];
        }
        if (RELU) {
#pragma unroll
            for (int j = 0; j < TN; ++j) outv[j] = fmaxf(outv[j], 0.0f);
        }
        float* cp = &C[(size_t)(m0 + ty * TM + i) * N + n0 + tx * TN];
#pragma unroll
        for (int v = 0; v < TN / 4; ++v)
            *(float4*)&cp[v * 4] = make_float4(outv[v * 4 + 0], outv[v * 4 + 1],
                                               outv[v * 4 + 2], outv[v * 4 + 3]);
    }
}

__global__ void __launch_bounds__(256) gemm2_kernel(const float* __restrict__ W,
                                                    const float* __restrict__ bias,
                                                    float* __restrict__ C)
{
    gemm_body<64, 128, 16, 4, 8, false>(g_H, W, bias, C, GK, COUT, FH);
}

// ---------------------------------------------------------------------------
extern "C" void kernel_launch(void* const* d_in, const int* in_sizes, int n_in,
                              void* d_out, int out_size)
{
    const float* keys   = (const float*)d_in[0];
    const float* points = (const float*)d_in[1];
    const float* feats  = (const float*)d_in[2];
    const float* wc0W   = (const float*)d_in[3];
    const float* wc0b   = (const float*)d_in[4];
    const float* wc1W   = (const float*)d_in[5];
    const float* wc1b   = (const float*)d_in[6];
    const float* wc2W   = (const float*)d_in[7];
    const float* wc2b   = (const float*)d_in[8];
    const float* fc0W   = (const float*)d_in[9];
    const float* fc0b   = (const float*)d_in[10];
    const float* fc1W   = (const float*)d_in[11];
    const float* fc1b   = (const float*)d_in[12];
    float* out = (float*)d_out;

    cudaFuncSetAttribute(gemm1_mma_kernel,
                         cudaFuncAttributeMaxDynamicSharedMemorySize, G1_SMEM);

    convw_kernel<<<FH * EDIM / 256, 256>>>(fc0W);
    knn_kernel<<<GK / 8, 256>>>(keys, points);
    edge_kernel<<<GK / 4, 128>>>(keys, points, feats,
                                 wc0W, wc0b, wc1W, wc1b, wc2W, wc2b);
    gemm1_mma_kernel<<<dim3(FH / 128, GK / 128), 256, G1_SMEM>>>(fc0b);
    gemm2_kernel<<<dim3(1, GK / 64), 256>>>(fc1W, fc1b, out);
}

// round 9
// speedup vs baseline: 1.8367x; 1.8367x over previous
#include <cuda_runtime.h>
#include <cuda_bf16.h>
#include <cstdint>

#define DEV_INLINE __device__ __forceinline__

constexpr int B_   = 4;
constexpr int K_   = 2048;
constexpr int P_   = 4096;
constexpr int NB   = 16;
constexpr int CIN  = 64;
constexpr int CMID = 32;
constexpr int FH   = 256;
constexpr int COUT = 128;
constexpr int GK   = B_ * K_;        // 8192 keys total
constexpr int EDIM = CMID * CIN;     // 2048

// Scratch (allocation-free rule: __device__ globals)
__device__ int            g_idx[GK * NB];
__device__ __nv_bfloat16  g_Ehi[(size_t)GK * EDIM];   // 32 MB
__device__ __nv_bfloat16  g_Elo[(size_t)GK * EDIM];   // 32 MB
__device__ __nv_bfloat16  g_Whi[(size_t)FH * EDIM];   // W0^T split, [256][2048]
__device__ __nv_bfloat16  g_Wlo[(size_t)FH * EDIM];
__device__ __nv_bfloat16  g_Hhi[(size_t)GK * FH];     // H split, [8192][256]
__device__ __nv_bfloat16  g_Hlo[(size_t)GK * FH];
__device__ __nv_bfloat16  g_W1hi[COUT * FH];          // W1^T split, [128][256]
__device__ __nv_bfloat16  g_W1lo[COUT * FH];

// ---------------------------------------------------------------------------
// PTX helpers (cp.async / ldmatrix / mma.sync — baseline sm_80+, plain sm_103 OK)
// ---------------------------------------------------------------------------
DEV_INLINE uint32_t smem_u32(const void* p) {
    return (uint32_t)__cvta_generic_to_shared(p);
}

DEV_INLINE void cp_async16(uint32_t dst, const void* src) {
    asm volatile("cp.async.cg.shared.global [%0], [%1], 16;"
                 :: "r"(dst), "l"(src) : "memory");
}
DEV_INLINE void cp_commit()  { asm volatile("cp.async.commit_group;" ::: "memory"); }
template <int N> DEV_INLINE void cp_wait() {
    asm volatile("cp.async.wait_group %0;" :: "n"(N) : "memory");
}

DEV_INLINE void ldm_x4(uint32_t* r, uint32_t addr) {
    asm volatile("ldmatrix.sync.aligned.m8n8.x4.shared.b16 {%0,%1,%2,%3}, [%4];"
                 : "=r"(r[0]), "=r"(r[1]), "=r"(r[2]), "=r"(r[3]) : "r"(addr));
}

DEV_INLINE void mma_bf16(float* d, const uint32_t* a, uint32_t b0, uint32_t b1) {
    asm volatile(
        "mma.sync.aligned.m16n8k16.row.col.f32.bf16.bf16.f32 "
        "{%0,%1,%2,%3}, {%4,%5,%6,%7}, {%8,%9}, {%0,%1,%2,%3};"
        : "+f"(d[0]), "+f"(d[1]), "+f"(d[2]), "+f"(d[3])
        : "r"(a[0]), "r"(a[1]), "r"(a[2]), "r"(a[3]), "r"(b0), "r"(b1));
}

// Split v0,v1 into bf16 hi (returned packed) and bf16 lo (out-param packed).
DEV_INLINE uint32_t pack_split(float v0, float v1, uint32_t& lo_out) {
    __nv_bfloat16 h0 = __float2bfloat16(v0);
    __nv_bfloat16 h1 = __float2bfloat16(v1);
    __nv_bfloat16 l0 = __float2bfloat16(v0 - __bfloat162float(h0));
    __nv_bfloat16 l1 = __float2bfloat16(v1 - __bfloat162float(h1));
    lo_out = ((uint32_t)__bfloat16_as_ushort(l1) << 16) | __bfloat16_as_ushort(l0);
    return ((uint32_t)__bfloat16_as_ushort(h1) << 16) | __bfloat16_as_ushort(h0);
}

// ---------------------------------------------------------------------------
// Kernel 1: KNN — 1 warp per key (verified; untouched)
// ---------------------------------------------------------------------------
__global__ void __launch_bounds__(256) knn_kernel(
    const float* __restrict__ keys, const float* __restrict__ points)
{
    __shared__ float sp[P_ * 3];
    const int warp = threadIdx.x >> 5;
    const int lane = threadIdx.x & 31;
    const int g = blockIdx.x * 8 + warp;
    const int b = g >> 11;

    const float* pb = points + (size_t)b * P_ * 3;
    for (int i = threadIdx.x; i < P_ * 3; i += 256) sp[i] = pb[i];
    __syncthreads();

    const float kx = keys[g * 3 + 0];
    const float ky = keys[g * 3 + 1];
    const float kz = keys[g * 3 + 2];

    float bd[NB]; int bi[NB];
#pragma unroll
    for (int j = 0; j < NB; ++j) { bd[j] = 3.4e38f; bi[j] = 0x7fffffff; }

    for (int p = lane; p < P_; p += 32) {
        float dx = __fsub_rn(sp[p * 3 + 0], kx);
        float dy = __fsub_rn(sp[p * 3 + 1], ky);
        float dz = __fsub_rn(sp[p * 3 + 2], kz);
        float d  = __fadd_rn(__fadd_rn(__fmul_rn(dx, dx), __fmul_rn(dy, dy)),
                             __fmul_rn(dz, dz));
        if (d < bd[NB - 1]) {
            float cd = d; int ci = p;
#pragma unroll
            for (int j = 0; j < NB; ++j) {
                bool  sw = (cd < bd[j]);
                float tf = sw ? bd[j] : cd;
                int   ti = sw ? bi[j] : ci;
                bd[j] = sw ? cd : bd[j];
                bi[j] = sw ? ci : bi[j];
                cd = tf; ci = ti;
            }
        }
    }

    int res_i = 0;
    for (int t = 0; t < NB; ++t) {
        float vd = bd[0]; int vi = bi[0]; int vl = lane;
#pragma unroll
        for (int off = 16; off > 0; off >>= 1) {
            float od = __shfl_xor_sync(0xffffffffu, vd, off);
            int   oi = __shfl_xor_sync(0xffffffffu, vi, off);
            int   ol = __shfl_xor_sync(0xffffffffu, vl, off);
            if (od < vd || (od == vd && oi < vi)) { vd = od; vi = oi; vl = ol; }
        }
        if (lane == t) res_i = vi;
        if (lane == vl) {
#pragma unroll
            for (int j = 0; j < NB - 1; ++j) { bd[j] = bd[j + 1]; bi[j] = bi[j + 1]; }
            bd[NB - 1] = 3.4e38f; bi[NB - 1] = 0x7fffffff;
        }
    }
    if (lane < NB) g_idx[g * NB + lane] = res_i;
}

// ---------------------------------------------------------------------------
// Kernel 2: per-edge weight MLP + aggregation -> E (bf16 hi/lo, packed stores).
// All 32 lanes active in MLP: 2 lanes per neighbor, 16 outputs each, partner
// exchange via shfl_xor(1). Aggregation: lane owns cols {2*lane, 2*lane+1}.
// ---------------------------------------------------------------------------
__global__ void __launch_bounds__(128) edge_kernel(
    const float* __restrict__ keys, const float* __restrict__ points,
    const float* __restrict__ feats,
    const float* __restrict__ w0, const float* __restrict__ b0,
    const float* __restrict__ w1, const float* __restrict__ b1,
    const float* __restrict__ w2, const float* __restrict__ b2)
{
    __shared__ __align__(16) float sw0[3][32];
    __shared__ float sb0[32], sb1[32], sb2[32];
    __shared__ __align__(16) float sw1t[32][32];   // [out][in]
    __shared__ __align__(16) float sw2t[32][32];
    __shared__ __align__(16) float sm_m[4][NB][32];
    __shared__ __align__(16) float sm_f[4][NB][CIN];

    const int t = threadIdx.x;
    const int w = t >> 5, lane = t & 31;

    for (int i = t; i < 96; i += 128) sw0[i / 32][i % 32] = w0[i];
    if (t < 32) { sb0[t] = b0[t]; sb1[t] = b1[t]; sb2[t] = b2[t]; }
    for (int i = t; i < 1024; i += 128) {
        sw1t[i % 32][i / 32] = w1[i];
        sw2t[i % 32][i / 32] = w2[i];
    }
    __syncthreads();

    const int g = blockIdx.x * 4 + w;
    const int b = g >> 11;

    const int n  = lane >> 1;          // neighbor handled by this lane pair
    const int jb = (lane & 1) * 16;    // output half

    const int gi = g_idx[g * NB + n];

    // Full-warp coalesced-ish feature gather: 256 float4 total, 8 per lane.
#pragma unroll
    for (int i = 0; i < 8; ++i) {
        const int ii = lane + i * 32;
        const int nn = ii >> 4, q = ii & 15;
        const int gin = __shfl_sync(0xffffffffu, gi, nn * 2);
        *(float4*)&sm_f[w][nn][q * 4] =
            *(const float4*)&feats[((size_t)b * P_ + gin) * CIN + q * 4];
    }

    // MLP (all lanes; 16 outputs each)
    const float rx = points[((size_t)b * P_ + gi) * 3 + 0] - keys[g * 3 + 0];
    const float ry = points[((size_t)b * P_ + gi) * 3 + 1] - keys[g * 3 + 1];
    const float rz = points[((size_t)b * P_ + gi) * 3 + 2] - keys[g * 3 + 2];

    float h1[16];
#pragma unroll
    for (int j = 0; j < 16; ++j) {
        const int jj = jb + j;
        h1[j] = fmaxf(fmaf(rx, sw0[0][jj], fmaf(ry, sw0[1][jj],
                      fmaf(rz, sw0[2][jj], sb0[jj]))), 0.0f);
    }
    float h1o[16];
#pragma unroll
    for (int j = 0; j < 16; ++j) h1o[j] = __shfl_xor_sync(0xffffffffu, h1[j], 1);

    float h2[16];
#pragma unroll
    for (int j = 0; j < 16; ++j) {
        const int jj = jb + j;
        float a = sb1[jj];
        const float4* wo = (const float4*)(sw1t[jj] + jb);          // own half
        const float4* wp = (const float4*)(sw1t[jj] + (jb ^ 16));   // partner half
#pragma unroll
        for (int q = 0; q < 4; ++q) {
            float4 v = wo[q];
            a = fmaf(h1[4 * q + 0], v.x, a);
            a = fmaf(h1[4 * q + 1], v.y, a);
            a = fmaf(h1[4 * q + 2], v.z, a);
            a = fmaf(h1[4 * q + 3], v.w, a);
            float4 u = wp[q];
            a = fmaf(h1o[4 * q + 0], u.x, a);
            a = fmaf(h1o[4 * q + 1], u.y, a);
            a = fmaf(h1o[4 * q + 2], u.z, a);
            a = fmaf(h1o[4 * q + 3], u.w, a);
        }
        h2[j] = fmaxf(a, 0.0f);
    }
    float h2o[16];
#pragma unroll
    for (int j = 0; j < 16; ++j) h2o[j] = __shfl_xor_sync(0xffffffffu, h2[j], 1);

#pragma unroll
    for (int j = 0; j < 16; ++j) {
        const int jj = jb + j;
        float a = sb2[jj];
        const float4* wo = (const float4*)(sw2t[jj] + jb);
        const float4* wp = (const float4*)(sw2t[jj] + (jb ^ 16));
#pragma unroll
        for (int q = 0; q < 4; ++q) {
            float4 v = wo[q];
            a = fmaf(h2[4 * q + 0], v.x, a);
            a = fmaf(h2[4 * q + 1], v.y, a);
            a = fmaf(h2[4 * q + 2], v.z, a);
            a = fmaf(h2[4 * q + 3], v.w, a);
            float4 u = wp[q];
            a = fmaf(h2o[4 * q + 0], u.x, a);
            a = fmaf(h2o[4 * q + 1], u.y, a);
            a = fmaf(h2o[4 * q + 2], u.z, a);
            a = fmaf(h2o[4 * q + 3], u.w, a);
        }
        sm_m[w][n][jj] = a;   // linear output, no relu
    }
    __syncwarp();

    // Aggregation: e[mc][c] = sum_n m[n][mc] * f[n][c]; lane owns c = 2*lane, 2*lane+1.
    float e0[32], e1[32];
#pragma unroll
    for (int j = 0; j < 32; ++j) { e0[j] = 0.0f; e1[j] = 0.0f; }

#pragma unroll
    for (int nn = 0; nn < NB; ++nn) {
        const float2 f = *(const float2*)&sm_f[w][nn][2 * lane];
        const float4* mp = (const float4*)sm_m[w][nn];
#pragma unroll
        for (int q = 0; q < 8; ++q) {
            float4 mv = mp[q];
            e0[4 * q + 0] = fmaf(mv.x, f.x, e0[4 * q + 0]);
            e1[4 * q + 0] = fmaf(mv.x, f.y, e1[4 * q + 0]);
            e0[4 * q + 1] = fmaf(mv.y, f.x, e0[4 * q + 1]);
            e1[4 * q + 1] = fmaf(mv.y, f.y, e1[4 * q + 1]);
            e0[4 * q + 2] = fmaf(mv.z, f.x, e0[4 * q + 2]);
            e1[4 * q + 2] = fmaf(mv.z, f.y, e1[4 * q + 2]);
            e0[4 * q + 3] = fmaf(mv.w, f.x, e0[4 * q + 3]);
            e1[4 * q + 3] = fmaf(mv.w, f.y, e1[4 * q + 3]);
        }
    }

    uint32_t* EhP = (uint32_t*)(g_Ehi + (size_t)g * EDIM);
    uint32_t* ElP = (uint32_t*)(g_Elo + (size_t)g * EDIM);
#pragma unroll
    for (int mc = 0; mc < 32; ++mc) {
        uint32_t lo;
        uint32_t hi = pack_split(e0[mc], e1[mc], lo);
        EhP[mc * 32 + lane] = hi;
        ElP[mc * 32 + lane] = lo;
    }
}

// ---------------------------------------------------------------------------
// Kernel 3: prep — W0 transpose-split (coalesced via smem tile) + W1 split.
// Blocks 0..511: W0 [2048][256] f32 -> Whi/Wlo [256][2048] bf16 (32x32 tiles).
// Blocks 512..639: W1 [256][128] f32 -> W1hi/W1lo [128][256] bf16.
// ---------------------------------------------------------------------------
__global__ void __launch_bounds__(256) prep_kernel(const float* __restrict__ W0,
                                                   const float* __restrict__ W1)
{
    const int bx = blockIdx.x;
    if (bx < 512) {
        __shared__ float tile[32][33];
        const int tx = threadIdx.x & 31, ty = threadIdx.x >> 5;
        const int k0 = (bx & 63) * 32, n0 = (bx >> 6) * 32;
#pragma unroll
        for (int i = 0; i < 4; ++i)
            tile[ty + i * 8][tx] = W0[(size_t)(k0 + ty + i * 8) * FH + n0 + tx];
        __syncthreads();
#pragma unroll
        for (int i = 0; i < 4; ++i) {
            const int nn = n0 + ty + i * 8, kk = k0 + tx;
            const float v = tile[tx][ty + i * 8];
            __nv_bfloat16 h = __float2bfloat16(v);
            g_Whi[(size_t)nn * EDIM + kk] = h;
            g_Wlo[(size_t)nn * EDIM + kk] = __float2bfloat16(v - __bfloat162float(h));
        }
    } else {
        const int idx = (bx - 512) * 256 + threadIdx.x;   // 0..32767
        const int nn = idx >> 8, kk = idx & 255;
        const float v = W1[kk * COUT + nn];
        __nv_bfloat16 h = __float2bfloat16(v);
        g_W1hi[nn * FH + kk] = h;
        g_W1lo[nn * FH + kk] = __float2bfloat16(v - __bfloat162float(h));
    }
}

// ---------------------------------------------------------------------------
// Kernel 4: gemm1 HMMA — H = relu(E @ W0 + b0), 3-term bf16 split, 128x128,
// BK=64, 2-stage cp.async. Epilogue emits H as packed bf16 hi/lo.
// ---------------------------------------------------------------------------
constexpr int G1_STAGE = 4 * 16384;
constexpr int G1_SMEM  = 2 * G1_STAGE;       // 131072
constexpr int G1_NI    = EDIM / 64;          // 32

__global__ void __launch_bounds__(256, 1) gemm1_mma_kernel(const float* __restrict__ bias)
{
    extern __shared__ char smem[];
    const uint32_t base = smem_u32(smem);
    const int tid  = threadIdx.x;
    const int wid  = tid >> 5;
    const int lane = tid & 31;
    const int m0 = blockIdx.y * 128;
    const int n0 = blockIdx.x * 128;
    const int warpM = (wid & 1) * 64;
    const int warpN = (wid >> 1) * 32;

    const __nv_bfloat16* srcA_hi = g_Ehi + (size_t)m0 * EDIM;
    const __nv_bfloat16* srcA_lo = g_Elo + (size_t)m0 * EDIM;
    const __nv_bfloat16* srcB_hi = g_Whi + (size_t)n0 * EDIM;
    const __nv_bfloat16* srcB_lo = g_Wlo + (size_t)n0 * EDIM;

    auto load_stage = [&](int it) {
        const uint32_t sb = base + (it & 1) * G1_STAGE;
        const int k0 = it * 64;
        const __nv_bfloat16* srcs[4] = {srcA_hi, srcA_lo, srcB_hi, srcB_lo};
#pragma unroll
        for (int sub = 0; sub < 4; ++sub) {
            const __nv_bfloat16* sp = srcs[sub] + k0;
            const uint32_t sbase = sb + sub * 16384;
#pragma unroll
            for (int j = 0; j < 4; ++j) {
                const int idx = tid + j * 256;
                const int r = idx >> 3, c = idx & 7;
                const uint32_t off = (uint32_t)idx * 16;
                const uint32_t dst = sbase + (off ^ ((off >> 3) & 0x70));
                cp_async16(dst, sp + (size_t)r * EDIM + c * 8);
            }
        }
    };

    float acc[4][4][4];
#pragma unroll
    for (int i = 0; i < 4; ++i)
#pragma unroll
        for (int j = 0; j < 4; ++j)
#pragma unroll
            for (int q = 0; q < 4; ++q) acc[i][j][q] = 0.0f;

    const int aRow = ((lane >> 3) & 1) * 8 + (lane & 7);
    const int aKof = (lane >> 4) * 8;
    const int bRow = ((lane >> 4) & 1) * 8 + (lane & 7);
    const int bKof = ((lane >> 3) & 1) * 8;

    load_stage(0);
    cp_commit();

    for (int it = 0; it < G1_NI; ++it) {
        if (it + 1 < G1_NI) {
            load_stage(it + 1);
            cp_commit();
            cp_wait<1>();
        } else {
            cp_wait<0>();
        }
        __syncthreads();

        const uint32_t sb = base + (it & 1) * G1_STAGE;
        const uint32_t sA_hi = sb;
        const uint32_t sA_lo = sb + 16384;
        const uint32_t sB_hi = sb + 32768;
        const uint32_t sB_lo = sb + 49152;

#pragma unroll
        for (int kk = 0; kk < 4; ++kk) {
            const int k0 = kk * 16;
            uint32_t ah[4][4], al[4][4], bh[2][4], bl[2][4];
#pragma unroll
            for (int mi = 0; mi < 4; ++mi) {
                const int row = warpM + mi * 16 + aRow;
                const int col = k0 + aKof;
                const uint32_t off = (uint32_t)(row * 128 + col * 2);
                const uint32_t sw  = off ^ ((off >> 3) & 0x70);
                ldm_x4(ah[mi], sA_hi + sw);
                ldm_x4(al[mi], sA_lo + sw);
            }
#pragma unroll
            for (int nj = 0; nj < 2; ++nj) {
                const int row = warpN + nj * 16 + bRow;
                const int col = k0 + bKof;
                const uint32_t off = (uint32_t)(row * 128 + col * 2);
                const uint32_t sw  = off ^ ((off >> 3) & 0x70);
                ldm_x4(bh[nj], sB_hi + sw);
                ldm_x4(bl[nj], sB_lo + sw);
            }
#pragma unroll
            for (int mi = 0; mi < 4; ++mi)
#pragma unroll
                for (int nj = 0; nj < 2; ++nj)
#pragma unroll
                    for (int nk = 0; nk < 2; ++nk) {
                        float* d = acc[mi][nj * 2 + nk];
                        mma_bf16(d, ah[mi], bh[nj][nk * 2], bh[nj][nk * 2 + 1]);
                        mma_bf16(d, ah[mi], bl[nj][nk * 2], bl[nj][nk * 2 + 1]);
                        mma_bf16(d, al[mi], bh[nj][nk * 2], bh[nj][nk * 2 + 1]);
                    }
        }
        __syncthreads();
    }

    // Epilogue: bias + relu, split to bf16 hi/lo, packed u32 stores.
#pragma unroll
    for (int mi = 0; mi < 4; ++mi) {
        const int row = m0 + warpM + mi * 16 + (lane >> 2);
#pragma unroll
        for (int ni = 0; ni < 4; ++ni) {
            const int col = n0 + warpN + ni * 8 + 2 * (lane & 3);
            const float b0v = bias[col], b1v = bias[col + 1];
            const float v0 = fmaxf(acc[mi][ni][0] + b0v, 0.0f);
            const float v1 = fmaxf(acc[mi][ni][1] + b1v, 0.0f);
            const float v2 = fmaxf(acc[mi][ni][2] + b0v, 0.0f);
            const float v3 = fmaxf(acc[mi][ni][3] + b1v, 0.0f);
            uint32_t lo01, lo23;
            const uint32_t hi01 = pack_split(v0, v1, lo01);
            const uint32_t hi23 = pack_split(v2, v3, lo23);
            ((uint32_t*)(g_Hhi + (size_t)row * FH))[col >> 1]       = hi01;
            ((uint32_t*)(g_Hlo + (size_t)row * FH))[col >> 1]       = lo01;
            ((uint32_t*)(g_Hhi + (size_t)(row + 8) * FH))[col >> 1] = hi23;
            ((uint32_t*)(g_Hlo + (size_t)(row + 8) * FH))[col >> 1] = lo23;
        }
    }
}

// ---------------------------------------------------------------------------
// Kernel 5: gemm2 HMMA — out = H @ W1 + b1, 3-term bf16 split.
// BM=64, BN=128 (full COUT), K=256 (4 chunks of 64), 2-stage cp.async.
// ---------------------------------------------------------------------------
constexpr int G2_A_BYTES = 64 * 64 * 2;        // 8192
constexpr int G2_B_BYTES = 128 * 64 * 2;       // 16384
constexpr int G2_STAGE   = 2 * G2_A_BYTES + 2 * G2_B_BYTES;   // 49152
constexpr int G2_SMEM    = 2 * G2_STAGE;       // 98304
constexpr int G2_NI      = FH / 64;            // 4

__global__ void __launch_bounds__(256, 1) gemm2_mma_kernel(const float* __restrict__ bias,
                                                           float* __restrict__ C)
{
    extern __shared__ char smem[];
    const uint32_t base = smem_u32(smem);
    const int tid  = threadIdx.x;
    const int wid  = tid >> 5;
    const int lane = tid & 31;
    const int m0 = blockIdx.y * 64;
    const int warpM = (wid & 1) * 32;
    const int warpN = (wid >> 1) * 32;

    const __nv_bfloat16* srcA_hi = g_Hhi + (size_t)m0 * FH;
    const __nv_bfloat16* srcA_lo = g_Hlo + (size_t)m0 * FH;

    auto load_stage = [&](int it) {
        const uint32_t sb = base + (it & 1) * G2_STAGE;
        const int k0 = it * 64;
        // A hi/lo: 64 rows x 64 bf16 = 512 cp16 each -> 2 iters of 256 threads
#pragma unroll
        for (int s = 0; s < 2; ++s) {
            const __nv_bfloat16* sp = (s == 0 ? srcA_hi : srcA_lo) + k0;
            const uint32_t sbase = sb + s * G2_A_BYTES;
#pragma unroll
            for (int j = 0; j < 2; ++j) {
                const int idx = tid + j * 256;              // 0..511
                const int r = idx >> 3, c = idx & 7;
                const uint32_t off = (uint32_t)idx * 16;
                const uint32_t dst = sbase + (off ^ ((off >> 3) & 0x70));
                cp_async16(dst, sp + (size_t)r * FH + c * 8);
            }
        }
        // B hi/lo: 128 rows x 64 bf16 = 1024 cp16 each -> 4 iters
#pragma unroll
        for (int s = 0; s < 2; ++s) {
            const __nv_bfloat16* sp = (s == 0 ? g_W1hi : g_W1lo) + k0;
            const uint32_t sbase = sb + 2 * G2_A_BYTES + s * G2_B_BYTES;
#pragma unroll
            for (int j = 0; j < 4; ++j) {
                const int idx = tid + j * 256;              // 0..1023
                const int r = idx >> 3, c = idx & 7;
                const uint32_t off = (uint32_t)idx * 16;
                const uint32_t dst = sbase + (off ^ ((off >> 3) & 0x70));
                cp_async16(dst, sp + (size_t)r * FH + c * 8);
            }
        }
    };

    float acc[2][4][4];
#pragma unroll
    for (int i = 0; i < 2; ++i)
#pragma unroll
        for (int j = 0; j < 4; ++j)
#pragma unroll
            for (int q = 0; q < 4; ++q) acc[i][j][q] = 0.0f;

    const int aRow = ((lane >> 3) & 1) * 8 + (lane & 7);
    const int aKof = (lane >> 4) * 8;
    const int bRow = ((lane >> 4) & 1) * 8 + (lane & 7);
    const int bKof = ((lane >> 3) & 1) * 8;

    load_stage(0);
    cp_commit();

    for (int it = 0; it < G2_NI; ++it) {
        if (it + 1 < G2_NI) {
            load_stage(it + 1);
            cp_commit();
            cp_wait<1>();
        } else {
            cp_wait<0>();
        }
        __syncthreads();

        const uint32_t sb = base + (it & 1) * G2_STAGE;
        const uint32_t sA_hi = sb;
        const uint32_t sA_lo = sb + G2_A_BYTES;
        const uint32_t sB_hi = sb + 2 * G2_A_BYTES;
        const uint32_t sB_lo = sb + 2 * G2_A_BYTES + G2_B_BYTES;

#pragma unroll
        for (int kk = 0; kk < 4; ++kk) {
            const int k0 = kk * 16;
            uint32_t ah[2][4], al[2][4], bh[2][4], bl[2][4];
#pragma unroll
            for (int mi = 0; mi < 2; ++mi) {
                const int row = warpM + mi * 16 + aRow;
                const int col = k0 + aKof;
                const uint32_t off = (uint32_t)(row * 128 + col * 2);
                const uint32_t sw  = off ^ ((off >> 3) & 0x70);
                ldm_x4(ah[mi], sA_hi + sw);
                ldm_x4(al[mi], sA_lo + sw);
            }
#pragma unroll
            for (int nj = 0; nj < 2; ++nj) {
                const int row = warpN + nj * 16 + bRow;
                const int col = k0 + bKof;
                const uint32_t off = (uint32_t)(row * 128 + col * 2);
                const uint32_t sw  = off ^ ((off >> 3) & 0x70);
                ldm_x4(bh[nj], sB_hi + sw);
                ldm_x4(bl[nj], sB_lo + sw);
            }
#pragma unroll
            for (int mi = 0; mi < 2; ++mi)
#pragma unroll
                for (int nj = 0; nj < 2; ++nj)
#pragma unroll
                    for (int nk = 0; nk < 2; ++nk) {
                        float* d = acc[mi][nj * 2 + nk];
                        mma_bf16(d, ah[mi], bh[nj][nk * 2], bh[nj][nk * 2 + 1]);
                        mma_bf16(d, ah[mi], bl[nj][nk * 2], bl[nj][nk * 2 + 1]);
                        mma_bf16(d, al[mi], bh[nj][nk * 2], bh[nj][nk * 2 + 1]);
                    }
        }
        __syncthreads();
    }

    // Epilogue: bias, fp32 out (no relu)
#pragma unroll
    for (int mi = 0; mi < 2; ++mi) {
        const int row = m0 + warpM + mi * 16 + (lane >> 2);
#pragma unroll
        for (int ni = 0; ni < 4; ++ni) {
            const int col = warpN + ni * 8 + 2 * (lane & 3);
            const float b0v = bias[col], b1v = bias[col + 1];
            float2 v0, v1;
            v0.x = acc[mi][ni][0] + b0v;
            v0.y = acc[mi][ni][1] + b1v;
            v1.x = acc[mi][ni][2] + b0v;
            v1.y = acc[mi][ni][3] + b1v;
            *(float2*)&C[(size_t)row * COUT + col]       = v0;
            *(float2*)&C[(size_t)(row + 8) * COUT + col] = v1;
        }
    }
}

// ---------------------------------------------------------------------------
extern "C" void kernel_launch(void* const* d_in, const int* in_sizes, int n_in,
                              void* d_out, int out_size)
{
    const float* keys   = (const float*)d_in[0];
    const float* points = (const float*)d_in[1];
    const float* feats  = (const float*)d_in[2];
    const float* wc0W   = (const float*)d_in[3];
    const float* wc0b   = (const float*)d_in[4];
    const float* wc1W   = (const float*)d_in[5];
    const float* wc1b   = (const float*)d_in[6];
    const float* wc2W   = (const float*)d_in[7];
    const float* wc2b   = (const float*)d_in[8];
    const float* fc0W   = (const float*)d_in[9];
    const float* fc0b   = (const float*)d_in[10];
    const float* fc1W   = (const float*)d_in[11];
    const float* fc1b   = (const float*)d_in[12];
    float* out = (float*)d_out;

    cudaFuncSetAttribute(gemm1_mma_kernel,
                         cudaFuncAttributeMaxDynamicSharedMemorySize, G1_SMEM);
    cudaFuncSetAttribute(gemm2_mma_kernel,
                         cudaFuncAttributeMaxDynamicSharedMemorySize, G2_SMEM);

    prep_kernel<<<640, 256>>>(fc0W, fc1W);
    knn_kernel<<<GK / 8, 256>>>(keys, points);
    edge_kernel<<<GK / 4, 128>>>(keys, points, feats,
                                 wc0W, wc0b, wc1W, wc1b, wc2W, wc2b);
    gemm1_mma_kernel<<<dim3(FH / 128, GK / 128), 256, G1_SMEM>>>(fc0b);
    gemm2_mma_kernel<<<dim3(1, GK / 64), 256, G2_SMEM>>>(fc1b, out);
}

// round 10
// speedup vs baseline: 2.6361x; 1.4352x over previous
#include <cuda_runtime.h>
#include <cuda_bf16.h>
#include <cstdint>

#define DEV_INLINE __device__ __forceinline__

constexpr int B_   = 4;
constexpr int K_   = 2048;
constexpr int P_   = 4096;
constexpr int NB   = 16;
constexpr int CIN  = 64;
constexpr int CMID = 32;
constexpr int FH   = 256;
constexpr int COUT = 128;
constexpr int GK   = B_ * K_;        // 8192 keys total
constexpr int EDIM = CMID * CIN;     // 2048

// Scratch (allocation-free rule: __device__ globals)
__device__ int            g_idx[GK * NB];
__device__ __nv_bfloat16  g_Ehi[(size_t)GK * EDIM];   // 32 MB
__device__ __nv_bfloat16  g_Elo[(size_t)GK * EDIM];   // 32 MB
__device__ __nv_bfloat16  g_Whi[(size_t)FH * EDIM];   // W0^T split, [256][2048]
__device__ __nv_bfloat16  g_Wlo[(size_t)FH * EDIM];
__device__ __nv_bfloat16  g_Hhi[(size_t)GK * FH];     // H split, [8192][256]
__device__ __nv_bfloat16  g_Hlo[(size_t)GK * FH];
__device__ __nv_bfloat16  g_W1hi[COUT * FH];          // W1^T split, [128][256]
__device__ __nv_bfloat16  g_W1lo[COUT * FH];

// ---------------------------------------------------------------------------
// PTX helpers (cp.async / ldmatrix / mma.sync — baseline sm_80+, plain sm_103 OK)
// ---------------------------------------------------------------------------
DEV_INLINE uint32_t smem_u32(const void* p) {
    return (uint32_t)__cvta_generic_to_shared(p);
}

DEV_INLINE void cp_async16(uint32_t dst, const void* src) {
    asm volatile("cp.async.cg.shared.global [%0], [%1], 16;"
                 :: "r"(dst), "l"(src) : "memory");
}
DEV_INLINE void cp_commit()  { asm volatile("cp.async.commit_group;" ::: "memory"); }
template <int N> DEV_INLINE void cp_wait() {
    asm volatile("cp.async.wait_group %0;" :: "n"(N) : "memory");
}

DEV_INLINE void ldm_x4(uint32_t* r, uint32_t addr) {
    asm volatile("ldmatrix.sync.aligned.m8n8.x4.shared.b16 {%0,%1,%2,%3}, [%4];"
                 : "=r"(r[0]), "=r"(r[1]), "=r"(r[2]), "=r"(r[3]) : "r"(addr));
}

DEV_INLINE void mma_bf16(float* d, const uint32_t* a, uint32_t b0, uint32_t b1) {
    asm volatile(
        "mma.sync.aligned.m16n8k16.row.col.f32.bf16.bf16.f32 "
        "{%0,%1,%2,%3}, {%4,%5,%6,%7}, {%8,%9}, {%0,%1,%2,%3};"
        : "+f"(d[0]), "+f"(d[1]), "+f"(d[2]), "+f"(d[3])
        : "r"(a[0]), "r"(a[1]), "r"(a[2]), "r"(a[3]), "r"(b0), "r"(b1));
}

// Split v0,v1 into bf16 hi (returned packed) and bf16 lo (out-param packed).
DEV_INLINE uint32_t pack_split(float v0, float v1, uint32_t& lo_out) {
    __nv_bfloat16 h0 = __float2bfloat16(v0);
    __nv_bfloat16 h1 = __float2bfloat16(v1);
    __nv_bfloat16 l0 = __float2bfloat16(v0 - __bfloat162float(h0));
    __nv_bfloat16 l1 = __float2bfloat16(v1 - __bfloat162float(h1));
    lo_out = ((uint32_t)__bfloat16_as_ushort(l1) << 16) | __bfloat16_as_ushort(l0);
    return ((uint32_t)__bfloat16_as_ushort(h1) << 16) | __bfloat16_as_ushort(h0);
}

// ---------------------------------------------------------------------------
// Kernel 1: KNN — 1 warp per key, WARP-WIDE distributed top-16.
// Lanes 0..15 hold the sorted (ascending) warp top-16 in registers; warpMax
// is the current 16th smallest, broadcast. Insertion rate ~16/i per warp step
// (~133 total), each a cheap shuffle shift — vs per-lane thresholds where the
// divergent insert fires ~every iteration.
// Distances use jax's exact mul/add order -> identical floats -> same set,
// and stable tie handling (scan order = increasing point index).
// ---------------------------------------------------------------------------
__global__ void __launch_bounds__(256) knn_kernel(
    const float* __restrict__ keys, const float* __restrict__ points)
{
    __shared__ float sp[P_ * 3];
    const int warp = threadIdx.x >> 5;
    const int lane = threadIdx.x & 31;
    const int g = blockIdx.x * 8 + warp;
    const int b = g >> 11;
    const unsigned FULL = 0xffffffffu;

    const float* pb = points + (size_t)b * P_ * 3;
    for (int i = threadIdx.x; i < P_ * 3; i += 256) sp[i] = pb[i];
    __syncthreads();

    const float kx = keys[g * 3 + 0];
    const float ky = keys[g * 3 + 1];
    const float kz = keys[g * 3 + 2];

    float ld = 3.4e38f;          // distributed list entry (lanes 0..15 valid)
    int   li = 0x7fffffff;
    float warpMax = 3.4e38f;     // current 16th smallest (uniform)

    for (int p = lane; p < P_; p += 32) {
        float dx = __fsub_rn(sp[p * 3 + 0], kx);
        float dy = __fsub_rn(sp[p * 3 + 1], ky);
        float dz = __fsub_rn(sp[p * 3 + 2], kz);
        float d  = __fadd_rn(__fadd_rn(__fmul_rn(dx, dx), __fmul_rn(dy, dy)),
                             __fmul_rn(dz, dz));

        unsigned hit = __ballot_sync(FULL, d < warpMax);
        while (hit) {
            const int src = __ffs(hit) - 1;
            hit &= hit - 1;
            const float dc = __shfl_sync(FULL, d, src);
            const int   ic = __shfl_sync(FULL, p, src);
            if (dc < warpMax) {   // recheck: warpMax tightens within this loop
                // position = count of list entries <= dc (stable: ties first)
                const unsigned bal =
                    __ballot_sync(FULL, (lane < NB) && (ld <= dc));
                const int pos = __popc(bal);
                const float pd = __shfl_up_sync(FULL, ld, 1);
                const int   pi = __shfl_up_sync(FULL, li, 1);
                if (lane >= pos && lane < NB) {
                    ld = (lane == pos) ? dc : pd;
                    li = (lane == pos) ? ic : pi;
                }
                warpMax = __shfl_sync(FULL, ld, NB - 1);
            }
        }
    }
    if (lane < NB) g_idx[g * NB + lane] = li;
}

// ---------------------------------------------------------------------------
// Kernel 2: per-edge weight MLP + aggregation -> E (bf16 hi/lo, packed stores).
// All 32 lanes active in MLP: 2 lanes per neighbor, 16 outputs each, partner
// exchange via shfl_xor(1). Aggregation: lane owns cols {2*lane, 2*lane+1}.
// ---------------------------------------------------------------------------
__global__ void __launch_bounds__(128) edge_kernel(
    const float* __restrict__ keys, const float* __restrict__ points,
    const float* __restrict__ feats,
    const float* __restrict__ w0, const float* __restrict__ b0,
    const float* __restrict__ w1, const float* __restrict__ b1,
    const float* __restrict__ w2, const float* __restrict__ b2)
{
    __shared__ __align__(16) float sw0[3][32];
    __shared__ float sb0[32], sb1[32], sb2[32];
    __shared__ __align__(16) float sw1t[32][32];   // [out][in]
    __shared__ __align__(16) float sw2t[32][32];
    __shared__ __align__(16) float sm_m[4][NB][32];
    __shared__ __align__(16) float sm_f[4][NB][CIN];

    const int t = threadIdx.x;
    const int w = t >> 5, lane = t & 31;

    for (int i = t; i < 96; i += 128) sw0[i / 32][i % 32] = w0[i];
    if (t < 32) { sb0[t] = b0[t]; sb1[t] = b1[t]; sb2[t] = b2[t]; }
    for (int i = t; i < 1024; i += 128) {
        sw1t[i % 32][i / 32] = w1[i];
        sw2t[i % 32][i / 32] = w2[i];
    }
    __syncthreads();

    const int g = blockIdx.x * 4 + w;
    const int b = g >> 11;

    const int n  = lane >> 1;          // neighbor handled by this lane pair
    const int jb = (lane & 1) * 16;    // output half

    const int gi = g_idx[g * NB + n];

    // Full-warp feature gather: 256 float4 total, 8 per lane.
#pragma unroll
    for (int i = 0; i < 8; ++i) {
        const int ii = lane + i * 32;
        const int nn = ii >> 4, q = ii & 15;
        const int gin = __shfl_sync(0xffffffffu, gi, nn * 2);
        *(float4*)&sm_f[w][nn][q * 4] =
            *(const float4*)&feats[((size_t)b * P_ + gin) * CIN + q * 4];
    }

    // MLP (all lanes; 16 outputs each)
    const float rx = points[((size_t)b * P_ + gi) * 3 + 0] - keys[g * 3 + 0];
    const float ry = points[((size_t)b * P_ + gi) * 3 + 1] - keys[g * 3 + 1];
    const float rz = points[((size_t)b * P_ + gi) * 3 + 2] - keys[g * 3 + 2];

    float h1[16];
#pragma unroll
    for (int j = 0; j < 16; ++j) {
        const int jj = jb + j;
        h1[j] = fmaxf(fmaf(rx, sw0[0][jj], fmaf(ry, sw0[1][jj],
                      fmaf(rz, sw0[2][jj], sb0[jj]))), 0.0f);
    }
    float h1o[16];
#pragma unroll
    for (int j = 0; j < 16; ++j) h1o[j] = __shfl_xor_sync(0xffffffffu, h1[j], 1);

    float h2[16];
#pragma unroll
    for (int j = 0; j < 16; ++j) {
        const int jj = jb + j;
        float a = sb1[jj];
        const float4* wo = (const float4*)(sw1t[jj] + jb);          // own half
        const float4* wp = (const float4*)(sw1t[jj] + (jb ^ 16));   // partner half
#pragma unroll
        for (int q = 0; q < 4; ++q) {
            float4 v = wo[q];
            a = fmaf(h1[4 * q + 0], v.x, a);
            a = fmaf(h1[4 * q + 1], v.y, a);
            a = fmaf(h1[4 * q + 2], v.z, a);
            a = fmaf(h1[4 * q + 3], v.w, a);
            float4 u = wp[q];
            a = fmaf(h1o[4 * q + 0], u.x, a);
            a = fmaf(h1o[4 * q + 1], u.y, a);
            a = fmaf(h1o[4 * q + 2], u.z, a);
            a = fmaf(h1o[4 * q + 3], u.w, a);
        }
        h2[j] = fmaxf(a, 0.0f);
    }
    float h2o[16];
#pragma unroll
    for (int j = 0; j < 16; ++j) h2o[j] = __shfl_xor_sync(0xffffffffu, h2[j], 1);

#pragma unroll
    for (int j = 0; j < 16; ++j) {
        const int jj = jb + j;
        float a = sb2[jj];
        const float4* wo = (const float4*)(sw2t[jj] + jb);
        const float4* wp = (const float4*)(sw2t[jj] + (jb ^ 16));
#pragma unroll
        for (int q = 0; q < 4; ++q) {
            float4 v = wo[q];
            a = fmaf(h2[4 * q + 0], v.x, a);
            a = fmaf(h2[4 * q + 1], v.y, a);
            a = fmaf(h2[4 * q + 2], v.z, a);
            a = fmaf(h2[4 * q + 3], v.w, a);
            float4 u = wp[q];
            a = fmaf(h2o[4 * q + 0], u.x, a);
            a = fmaf(h2o[4 * q + 1], u.y, a);
            a = fmaf(h2o[4 * q + 2], u.z, a);
            a = fmaf(h2o[4 * q + 3], u.w, a);
        }
        sm_m[w][n][jj] = a;   // linear output, no relu
    }
    __syncwarp();

    // Aggregation: e[mc][c] = sum_n m[n][mc] * f[n][c]; lane owns c = 2*lane, 2*lane+1.
    float e0[32], e1[32];
#pragma unroll
    for (int j = 0; j < 32; ++j) { e0[j] = 0.0f; e1[j] = 0.0f; }

#pragma unroll
    for (int nn = 0; nn < NB; ++nn) {
        const float2 f = *(const float2*)&sm_f[w][nn][2 * lane];
        const float4* mp = (const float4*)sm_m[w][nn];
#pragma unroll
        for (int q = 0; q < 8; ++q) {
            float4 mv = mp[q];
            e0[4 * q + 0] = fmaf(mv.x, f.x, e0[4 * q + 0]);
            e1[4 * q + 0] = fmaf(mv.x, f.y, e1[4 * q + 0]);
            e0[4 * q + 1] = fmaf(mv.y, f.x, e0[4 * q + 1]);
            e1[4 * q + 1] = fmaf(mv.y, f.y, e1[4 * q + 1]);
            e0[4 * q + 2] = fmaf(mv.z, f.x, e0[4 * q + 2]);
            e1[4 * q + 2] = fmaf(mv.z, f.y, e1[4 * q + 2]);
            e0[4 * q + 3] = fmaf(mv.w, f.x, e0[4 * q + 3]);
            e1[4 * q + 3] = fmaf(mv.w, f.y, e1[4 * q + 3]);
        }
    }

    uint32_t* EhP = (uint32_t*)(g_Ehi + (size_t)g * EDIM);
    uint32_t* ElP = (uint32_t*)(g_Elo + (size_t)g * EDIM);
#pragma unroll
    for (int mc = 0; mc < 32; ++mc) {
        uint32_t lo;
        uint32_t hi = pack_split(e0[mc], e1[mc], lo);
        EhP[mc * 32 + lane] = hi;
        ElP[mc * 32 + lane] = lo;
    }
}

// ---------------------------------------------------------------------------
// Kernel 3: prep — W0 transpose-split (coalesced via smem tile) + W1 split.
// ---------------------------------------------------------------------------
__global__ void __launch_bounds__(256) prep_kernel(const float* __restrict__ W0,
                                                   const float* __restrict__ W1)
{
    const int bx = blockIdx.x;
    if (bx < 512) {
        __shared__ float tile[32][33];
        const int tx = threadIdx.x & 31, ty = threadIdx.x >> 5;
        const int k0 = (bx & 63) * 32, n0 = (bx >> 6) * 32;
#pragma unroll
        for (int i = 0; i < 4; ++i)
            tile[ty + i * 8][tx] = W0[(size_t)(k0 + ty + i * 8) * FH + n0 + tx];
        __syncthreads();
#pragma unroll
        for (int i = 0; i < 4; ++i) {
            const int nn = n0 + ty + i * 8, kk = k0 + tx;
            const float v = tile[tx][ty + i * 8];
            __nv_bfloat16 h = __float2bfloat16(v);
            g_Whi[(size_t)nn * EDIM + kk] = h;
            g_Wlo[(size_t)nn * EDIM + kk] = __float2bfloat16(v - __bfloat162float(h));
        }
    } else {
        const int idx = (bx - 512) * 256 + threadIdx.x;   // 0..32767
        const int nn = idx >> 8, kk = idx & 255;
        const float v = W1[kk * COUT + nn];
        __nv_bfloat16 h = __float2bfloat16(v);
        g_W1hi[nn * FH + kk] = h;
        g_W1lo[nn * FH + kk] = __float2bfloat16(v - __bfloat162float(h));
    }
}

// ---------------------------------------------------------------------------
// Kernel 4: gemm1 HMMA — H = relu(E @ W0 + b0), 3-term bf16 split, 128x128,
// BK=64, 2-stage cp.async. Epilogue emits H as packed bf16 hi/lo.
// ---------------------------------------------------------------------------
constexpr int G1_STAGE = 4 * 16384;
constexpr int G1_SMEM  = 2 * G1_STAGE;       // 131072
constexpr int G1_NI    = EDIM / 64;          // 32

__global__ void __launch_bounds__(256, 1) gemm1_mma_kernel(const float* __restrict__ bias)
{
    extern __shared__ char smem[];
    const uint32_t base = smem_u32(smem);
    const int tid  = threadIdx.x;
    const int wid  = tid >> 5;
    const int lane = tid & 31;
    const int m0 = blockIdx.y * 128;
    const int n0 = blockIdx.x * 128;
    const int warpM = (wid & 1) * 64;
    const int warpN = (wid >> 1) * 32;

    const __nv_bfloat16* srcA_hi = g_Ehi + (size_t)m0 * EDIM;
    const __nv_bfloat16* srcA_lo = g_Elo + (size_t)m0 * EDIM;
    const __nv_bfloat16* srcB_hi = g_Whi + (size_t)n0 * EDIM;
    const __nv_bfloat16* srcB_lo = g_Wlo + (size_t)n0 * EDIM;

    auto load_stage = [&](int it) {
        const uint32_t sb = base + (it & 1) * G1_STAGE;
        const int k0 = it * 64;
        const __nv_bfloat16* srcs[4] = {srcA_hi, srcA_lo, srcB_hi, srcB_lo};
#pragma unroll
        for (int sub = 0; sub < 4; ++sub) {
            const __nv_bfloat16* sp = srcs[sub] + k0;
            const uint32_t sbase = sb + sub * 16384;
#pragma unroll
            for (int j = 0; j < 4; ++j) {
                const int idx = tid + j * 256;
                const int r = idx >> 3, c = idx & 7;
                const uint32_t off = (uint32_t)idx * 16;
                const uint32_t dst = sbase + (off ^ ((off >> 3) & 0x70));
                cp_async16(dst, sp + (size_t)r * EDIM + c * 8);
            }
        }
    };

    float acc[4][4][4];
#pragma unroll
    for (int i = 0; i < 4; ++i)
#pragma unroll
        for (int j = 0; j < 4; ++j)
#pragma unroll
            for (int q = 0; q < 4; ++q) acc[i][j][q] = 0.0f;

    const int aRow = ((lane >> 3) & 1) * 8 + (lane & 7);
    const int aKof = (lane >> 4) * 8;
    const int bRow = ((lane >> 4) & 1) * 8 + (lane & 7);
    const int bKof = ((lane >> 3) & 1) * 8;

    load_stage(0);
    cp_commit();

    for (int it = 0; it < G1_NI; ++it) {
        if (it + 1 < G1_NI) {
            load_stage(it + 1);
            cp_commit();
            cp_wait<1>();
        } else {
            cp_wait<0>();
        }
        __syncthreads();

        const uint32_t sb = base + (it & 1) * G1_STAGE;
        const uint32_t sA_hi = sb;
        const uint32_t sA_lo = sb + 16384;
        const uint32_t sB_hi = sb + 32768;
        const uint32_t sB_lo = sb + 49152;

#pragma unroll
        for (int kk = 0; kk < 4; ++kk) {
            const int k0 = kk * 16;
            uint32_t ah[4][4], al[4][4], bh[2][4], bl[2][4];
#pragma unroll
            for (int mi = 0; mi < 4; ++mi) {
                const int row = warpM + mi * 16 + aRow;
                const int col = k0 + aKof;
                const uint32_t off = (uint32_t)(row * 128 + col * 2);
                const uint32_t sw  = off ^ ((off >> 3) & 0x70);
                ldm_x4(ah[mi], sA_hi + sw);
                ldm_x4(al[mi], sA_lo + sw);
            }
#pragma unroll
            for (int nj = 0; nj < 2; ++nj) {
                const int row = warpN + nj * 16 + bRow;
                const int col = k0 + bKof;
                const uint32_t off = (uint32_t)(row * 128 + col * 2);
                const uint32_t sw  = off ^ ((off >> 3) & 0x70);
                ldm_x4(bh[nj], sB_hi + sw);
                ldm_x4(bl[nj], sB_lo + sw);
            }
#pragma unroll
            for (int mi = 0; mi < 4; ++mi)
#pragma unroll
                for (int nj = 0; nj < 2; ++nj)
#pragma unroll
                    for (int nk = 0; nk < 2; ++nk) {
                        float* d = acc[mi][nj * 2 + nk];
                        mma_bf16(d, ah[mi], bh[nj][nk * 2], bh[nj][nk * 2 + 1]);
                        mma_bf16(d, ah[mi], bl[nj][nk * 2], bl[nj][nk * 2 + 1]);
                        mma_bf16(d, al[mi], bh[nj][nk * 2], bh[nj][nk * 2 + 1]);
                    }
        }
        __syncthreads();
    }

    // Epilogue: bias + relu, split to bf16 hi/lo, packed u32 stores.
#pragma unroll
    for (int mi = 0; mi < 4; ++mi) {
        const int row = m0 + warpM + mi * 16 + (lane >> 2);
#pragma unroll
        for (int ni = 0; ni < 4; ++ni) {
            const int col = n0 + warpN + ni * 8 + 2 * (lane & 3);
            const float b0v = bias[col], b1v = bias[col + 1];
            const float v0 = fmaxf(acc[mi][ni][0] + b0v, 0.0f);
            const float v1 = fmaxf(acc[mi][ni][1] + b1v, 0.0f);
            const float v2 = fmaxf(acc[mi][ni][2] + b0v, 0.0f);
            const float v3 = fmaxf(acc[mi][ni][3] + b1v, 0.0f);
            uint32_t lo01, lo23;
            const uint32_t hi01 = pack_split(v0, v1, lo01);
            const uint32_t hi23 = pack_split(v2, v3, lo23);
            ((uint32_t*)(g_Hhi + (size_t)row * FH))[col >> 1]       = hi01;
            ((uint32_t*)(g_Hlo + (size_t)row * FH))[col >> 1]       = lo01;
            ((uint32_t*)(g_Hhi + (size_t)(row + 8) * FH))[col >> 1] = hi23;
            ((uint32_t*)(g_Hlo + (size_t)(row + 8) * FH))[col >> 1] = lo23;
        }
    }
}

// ---------------------------------------------------------------------------
// Kernel 5: gemm2 HMMA — out = H @ W1 + b1, 3-term bf16 split.
// BM=64, BN=128 (full COUT), K=256 (4 chunks of 64), 2-stage cp.async.
// ---------------------------------------------------------------------------
constexpr int G2_A_BYTES = 64 * 64 * 2;        // 8192
constexpr int G2_B_BYTES = 128 * 64 * 2;       // 16384
constexpr int G2_STAGE   = 2 * G2_A_BYTES + 2 * G2_B_BYTES;   // 49152
constexpr int G2_SMEM    = 2 * G2_STAGE;       // 98304
constexpr int G2_NI      = FH / 64;            // 4

__global__ void __launch_bounds__(256, 1) gemm2_mma_kernel(const float* __restrict__ bias,
                                                           float* __restrict__ C)
{
    extern __shared__ char smem[];
    const uint32_t base = smem_u32(smem);
    const int tid  = threadIdx.x;
    const int wid  = tid >> 5;
    const int lane = tid & 31;
    const int m0 = blockIdx.y * 64;
    const int warpM = (wid & 1) * 32;
    const int warpN = (wid >> 1) * 32;

    const __nv_bfloat16* srcA_hi = g_Hhi + (size_t)m0 * FH;
    const __nv_bfloat16* srcA_lo = g_Hlo + (size_t)m0 * FH;

    auto load_stage = [&](int it) {
        const uint32_t sb = base + (it & 1) * G2_STAGE;
        const int k0 = it * 64;
#pragma unroll
        for (int s = 0; s < 2; ++s) {
            const __nv_bfloat16* sp = (s == 0 ? srcA_hi : srcA_lo) + k0;
            const uint32_t sbase = sb + s * G2_A_BYTES;
#pragma unroll
            for (int j = 0; j < 2; ++j) {
                const int idx = tid + j * 256;              // 0..511
                const int r = idx >> 3, c = idx & 7;
                const uint32_t off = (uint32_t)idx * 16;
                const uint32_t dst = sbase + (off ^ ((off >> 3) & 0x70));
                cp_async16(dst, sp + (size_t)r * FH + c * 8);
            }
        }
#pragma unroll
        for (int s = 0; s < 2; ++s) {
            const __nv_bfloat16* sp = (s == 0 ? g_W1hi : g_W1lo) + k0;
            const uint32_t sbase = sb + 2 * G2_A_BYTES + s * G2_B_BYTES;
#pragma unroll
            for (int j = 0; j < 4; ++j) {
                const int idx = tid + j * 256;              // 0..1023
                const int r = idx >> 3, c = idx & 7;
                const uint32_t off = (uint32_t)idx * 16;
                const uint32_t dst = sbase + (off ^ ((off >> 3) & 0x70));
                cp_async16(dst, sp + (size_t)r * FH + c * 8);
            }
        }
    };

    float acc[2][4][4];
#pragma unroll
    for (int i = 0; i < 2; ++i)
#pragma unroll
        for (int j = 0; j < 4; ++j)
#pragma unroll
            for (int q = 0; q < 4; ++q) acc[i][j][q] = 0.0f;

    const int aRow = ((lane >> 3) & 1) * 8 + (lane & 7);
    const int aKof = (lane >> 4) * 8;
    const int bRow = ((lane >> 4) & 1) * 8 + (lane & 7);
    const int bKof = ((lane >> 3) & 1) * 8;

    load_stage(0);
    cp_commit();

    for (int it = 0; it < G2_NI; ++it) {
        if (it + 1 < G2_NI) {
            load_stage(it + 1);
            cp_commit();
            cp_wait<1>();
        } else {
            cp_wait<0>();
        }
        __syncthreads();

        const uint32_t sb = base + (it & 1) * G2_STAGE;
        const uint32_t sA_hi = sb;
        const uint32_t sA_lo = sb + G2_A_BYTES;
        const uint32_t sB_hi = sb + 2 * G2_A_BYTES;
        const uint32_t sB_lo = sb + 2 * G2_A_BYTES + G2_B_BYTES;

#pragma unroll
        for (int kk = 0; kk < 4; ++kk) {
            const int k0 = kk * 16;
            uint32_t ah[2][4], al[2][4], bh[2][4], bl[2][4];
#pragma unroll
            for (int mi = 0; mi < 2; ++mi) {
                const int row = warpM + mi * 16 + aRow;
                const int col = k0 + aKof;
                const uint32_t off = (uint32_t)(row * 128 + col * 2);
                const uint32_t sw  = off ^ ((off >> 3) & 0x70);
                ldm_x4(ah[mi], sA_hi + sw);
                ldm_x4(al[mi], sA_lo + sw);
            }
#pragma unroll
            for (int nj = 0; nj < 2; ++nj) {
                const int row = warpN + nj * 16 + bRow;
                const int col = k0 + bKof;
                const uint32_t off = (uint32_t)(row * 128 + col * 2);
                const uint32_t sw  = off ^ ((off >> 3) & 0x70);
                ldm_x4(bh[nj], sB_hi + sw);
                ldm_x4(bl[nj], sB_lo + sw);
            }
#pragma unroll
            for (int mi = 0; mi < 2; ++mi)
#pragma unroll
                for (int nj = 0; nj < 2; ++nj)
#pragma unroll
                    for (int nk = 0; nk < 2; ++nk) {
                        float* d = acc[mi][nj * 2 + nk];
                        mma_bf16(d, ah[mi], bh[nj][nk * 2], bh[nj][nk * 2 + 1]);
                        mma_bf16(d, ah[mi], bl[nj][nk * 2], bl[nj][nk * 2 + 1]);
                        mma_bf16(d, al[mi], bh[nj][nk * 2], bh[nj][nk * 2 + 1]);
                    }
        }
        __syncthreads();
    }

    // Epilogue: bias, fp32 out (no relu)
#pragma unroll
    for (int mi = 0; mi < 2; ++mi) {
        const int row = m0 + warpM + mi * 16 + (lane >> 2);
#pragma unroll
        for (int ni = 0; ni < 4; ++ni) {
            const int col = warpN + ni * 8 + 2 * (lane & 3);
            const float b0v = bias[col], b1v = bias[col + 1];
            float2 v0, v1;
            v0.x = acc[mi][ni][0] + b0v;
            v0.y = acc[mi][ni][1] + b1v;
            v1.x = acc[mi][ni][2] + b0v;
            v1.y = acc[mi][ni][3] + b1v;
            *(float2*)&C[(size_t)row * COUT + col]       = v0;
            *(float2*)&C[(size_t)(row + 8) * COUT + col] = v1;
        }
    }
}

// ---------------------------------------------------------------------------
extern "C" void kernel_launch(void* const* d_in, const int* in_sizes, int n_in,
                              void* d_out, int out_size)
{
    const float* keys   = (const float*)d_in[0];
    const float* points = (const float*)d_in[1];
    const float* feats  = (const float*)d_in[2];
    const float* wc0W   = (const float*)d_in[3];
    const float* wc0b   = (const float*)d_in[4];
    const float* wc1W   = (const float*)d_in[5];
    const float* wc1b   = (const float*)d_in[6];
    const float* wc2W   = (const float*)d_in[7];
    const float* wc2b   = (const float*)d_in[8];
    const float* fc0W   = (const float*)d_in[9];
    const float* fc0b   = (const float*)d_in[10];
    const float* fc1W   = (const float*)d_in[11];
    const float* fc1b   = (const float*)d_in[12];
    float* out = (float*)d_out;

    cudaFuncSetAttribute(gemm1_mma_kernel,
                         cudaFuncAttributeMaxDynamicSharedMemorySize, G1_SMEM);
    cudaFuncSetAttribute(gemm2_mma_kernel,
                         cudaFuncAttributeMaxDynamicSharedMemorySize, G2_SMEM);

    prep_kernel<<<640, 256>>>(fc0W, fc1W);
    knn_kernel<<<GK / 8, 256>>>(keys, points);
    edge_kernel<<<GK / 4, 128>>>(keys, points, feats,
                                 wc0W, wc0b, wc1W, wc1b, wc2W, wc2b);
    gemm1_mma_kernel<<<dim3(FH / 128, GK / 128), 256, G1_SMEM>>>(fc0b);
    gemm2_mma_kernel<<<dim3(1, GK / 64), 256, G2_SMEM>>>(fc1b, out);
}

// round 11
// speedup vs baseline: 2.7553x; 1.0452x over previous
#include <cuda_runtime.h>
#include <cuda_bf16.h>
#include <cstdint>

#define DEV_INLINE __device__ __forceinline__

constexpr int B_   = 4;
constexpr int K_   = 2048;
constexpr int P_   = 4096;
constexpr int NB   = 16;
constexpr int CIN  = 64;
constexpr int CMID = 32;
constexpr int FH   = 256;
constexpr int COUT = 128;
constexpr int GK   = B_ * K_;        // 8192 keys total
constexpr int EDIM = CMID * CIN;     // 2048

// Scratch (allocation-free rule: __device__ globals)
__device__ int            g_idx[GK * NB];
__device__ __nv_bfloat16  g_Ehi[(size_t)GK * EDIM];   // 32 MB
__device__ __nv_bfloat16  g_Elo[(size_t)GK * EDIM];   // 32 MB
__device__ __nv_bfloat16  g_Whi[(size_t)FH * EDIM];   // W0^T split, [256][2048]
__device__ __nv_bfloat16  g_Wlo[(size_t)FH * EDIM];
__device__ __nv_bfloat16  g_Hhi[(size_t)GK * FH];     // H split, [8192][256]
__device__ __nv_bfloat16  g_Hlo[(size_t)GK * FH];
__device__ __nv_bfloat16  g_W1hi[COUT * FH];          // W1^T split, [128][256]
__device__ __nv_bfloat16  g_W1lo[COUT * FH];

// ---------------------------------------------------------------------------
// PTX helpers (cp.async / ldmatrix / mma.sync — baseline sm_80+, plain sm_103 OK)
// ---------------------------------------------------------------------------
DEV_INLINE uint32_t smem_u32(const void* p) {
    return (uint32_t)__cvta_generic_to_shared(p);
}

DEV_INLINE void cp_async16(uint32_t dst, const void* src) {
    asm volatile("cp.async.cg.shared.global [%0], [%1], 16;"
                 :: "r"(dst), "l"(src) : "memory");
}
DEV_INLINE void cp_commit()  { asm volatile("cp.async.commit_group;" ::: "memory"); }
template <int N> DEV_INLINE void cp_wait() {
    asm volatile("cp.async.wait_group %0;" :: "n"(N) : "memory");
}

DEV_INLINE void ldm_x4(uint32_t* r, uint32_t addr) {
    asm volatile("ldmatrix.sync.aligned.m8n8.x4.shared.b16 {%0,%1,%2,%3}, [%4];"
                 : "=r"(r[0]), "=r"(r[1]), "=r"(r[2]), "=r"(r[3]) : "r"(addr));
}

DEV_INLINE void mma_bf16(float* d, const uint32_t* a, uint32_t b0, uint32_t b1) {
    asm volatile(
        "mma.sync.aligned.m16n8k16.row.col.f32.bf16.bf16.f32 "
        "{%0,%1,%2,%3}, {%4,%5,%6,%7}, {%8,%9}, {%0,%1,%2,%3};"
        : "+f"(d[0]), "+f"(d[1]), "+f"(d[2]), "+f"(d[3])
        : "r"(a[0]), "r"(a[1]), "r"(a[2]), "r"(a[3]), "r"(b0), "r"(b1));
}

// Split v0,v1 into bf16 hi (returned packed) and bf16 lo (out-param packed).
DEV_INLINE uint32_t pack_split(float v0, float v1, uint32_t& lo_out) {
    __nv_bfloat16 h0 = __float2bfloat16(v0);
    __nv_bfloat16 h1 = __float2bfloat16(v1);
    __nv_bfloat16 l0 = __float2bfloat16(v0 - __bfloat162float(h0));
    __nv_bfloat16 l1 = __float2bfloat16(v1 - __bfloat162float(h1));
    lo_out = ((uint32_t)__bfloat16_as_ushort(l1) << 16) | __bfloat16_as_ushort(l0);
    return ((uint32_t)__bfloat16_as_ushort(h1) << 16) | __bfloat16_as_ushort(h0);
}

// ---------------------------------------------------------------------------
// Kernel 1: fused prep + KNN.
// Blocks 0..511:  W0 [2048][256] f32 -> Whi/Wlo [256][2048] bf16 (32x32 tiles).
// Blocks 512..639: W1 [256][128] f32 -> W1hi/W1lo [128][256] bf16.
// Blocks 640..1663: KNN (warp-wide distributed top-16, verified round 10).
// ---------------------------------------------------------------------------
__global__ void __launch_bounds__(256) knn_prep_kernel(
    const float* __restrict__ keys, const float* __restrict__ points,
    const float* __restrict__ W0, const float* __restrict__ W1)
{
    __shared__ float sp[P_ * 3];   // 48KB: points tile for knn / transpose tile for prep
    const int bx = blockIdx.x;

    if (bx < 512) {
        // --- W0 transpose-split ---
        float (*tile)[33] = (float(*)[33])sp;
        const int tx = threadIdx.x & 31, ty = threadIdx.x >> 5;
        const int k0 = (bx & 63) * 32, n0 = (bx >> 6) * 32;
#pragma unroll
        for (int i = 0; i < 4; ++i)
            tile[ty + i * 8][tx] = W0[(size_t)(k0 + ty + i * 8) * FH + n0 + tx];
        __syncthreads();
#pragma unroll
        for (int i = 0; i < 4; ++i) {
            const int nn = n0 + ty + i * 8, kk = k0 + tx;
            const float v = tile[tx][ty + i * 8];
            __nv_bfloat16 h = __float2bfloat16(v);
            g_Whi[(size_t)nn * EDIM + kk] = h;
            g_Wlo[(size_t)nn * EDIM + kk] = __float2bfloat16(v - __bfloat162float(h));
        }
        return;
    }
    if (bx < 640) {
        // --- W1 split ---
        const int idx = (bx - 512) * 256 + threadIdx.x;   // 0..32767
        const int nn = idx >> 8, kk = idx & 255;
        const float v = W1[kk * COUT + nn];
        __nv_bfloat16 h = __float2bfloat16(v);
        g_W1hi[nn * FH + kk] = h;
        g_W1lo[nn * FH + kk] = __float2bfloat16(v - __bfloat162float(h));
        return;
    }

    // --- KNN ---
    const int kb = bx - 640;
    const int warp = threadIdx.x >> 5;
    const int lane = threadIdx.x & 31;
    const int g = kb * 8 + warp;
    const int b = g >> 11;
    const unsigned FULL = 0xffffffffu;

    const float* pb = points + (size_t)b * P_ * 3;
    for (int i = threadIdx.x; i < P_ * 3; i += 256) sp[i] = pb[i];
    __syncthreads();

    const float kx = keys[g * 3 + 0];
    const float ky = keys[g * 3 + 1];
    const float kz = keys[g * 3 + 2];

    float ld = 3.4e38f;          // distributed list entry (lanes 0..15 valid)
    int   li = 0x7fffffff;
    float warpMax = 3.4e38f;     // current 16th smallest (uniform)

    for (int p = lane; p < P_; p += 32) {
        float dx = __fsub_rn(sp[p * 3 + 0], kx);
        float dy = __fsub_rn(sp[p * 3 + 1], ky);
        float dz = __fsub_rn(sp[p * 3 + 2], kz);
        float d  = __fadd_rn(__fadd_rn(__fmul_rn(dx, dx), __fmul_rn(dy, dy)),
                             __fmul_rn(dz, dz));

        unsigned hit = __ballot_sync(FULL, d < warpMax);
        while (hit) {
            const int src = __ffs(hit) - 1;
            hit &= hit - 1;
            const float dc = __shfl_sync(FULL, d, src);
            const int   ic = __shfl_sync(FULL, p, src);
            if (dc < warpMax) {   // recheck: warpMax tightens within this loop
                const unsigned bal =
                    __ballot_sync(FULL, (lane < NB) && (ld <= dc));
                const int pos = __popc(bal);
                const float pd = __shfl_up_sync(FULL, ld, 1);
                const int   pi = __shfl_up_sync(FULL, li, 1);
                if (lane >= pos && lane < NB) {
                    ld = (lane == pos) ? dc : pd;
                    li = (lane == pos) ? ic : pi;
                }
                warpMax = __shfl_sync(FULL, ld, NB - 1);
            }
        }
    }
    if (lane < NB) g_idx[g * NB + lane] = li;
}

// ---------------------------------------------------------------------------
// Kernel 2: per-edge weight MLP + aggregation -> E (bf16 hi/lo, packed stores).
// (verified round 10; unchanged)
// ---------------------------------------------------------------------------
__global__ void __launch_bounds__(128) edge_kernel(
    const float* __restrict__ keys, const float* __restrict__ points,
    const float* __restrict__ feats,
    const float* __restrict__ w0, const float* __restrict__ b0,
    const float* __restrict__ w1, const float* __restrict__ b1,
    const float* __restrict__ w2, const float* __restrict__ b2)
{
    __shared__ __align__(16) float sw0[3][32];
    __shared__ float sb0[32], sb1[32], sb2[32];
    __shared__ __align__(16) float sw1t[32][32];   // [out][in]
    __shared__ __align__(16) float sw2t[32][32];
    __shared__ __align__(16) float sm_m[4][NB][32];
    __shared__ __align__(16) float sm_f[4][NB][CIN];

    const int t = threadIdx.x;
    const int w = t >> 5, lane = t & 31;

    for (int i = t; i < 96; i += 128) sw0[i / 32][i % 32] = w0[i];
    if (t < 32) { sb0[t] = b0[t]; sb1[t] = b1[t]; sb2[t] = b2[t]; }
    for (int i = t; i < 1024; i += 128) {
        sw1t[i % 32][i / 32] = w1[i];
        sw2t[i % 32][i / 32] = w2[i];
    }
    __syncthreads();

    const int g = blockIdx.x * 4 + w;
    const int b = g >> 11;

    const int n  = lane >> 1;          // neighbor handled by this lane pair
    const int jb = (lane & 1) * 16;    // output half

    const int gi = g_idx[g * NB + n];

    // Full-warp feature gather: 256 float4 total, 8 per lane.
#pragma unroll
    for (int i = 0; i < 8; ++i) {
        const int ii = lane + i * 32;
        const int nn = ii >> 4, q = ii & 15;
        const int gin = __shfl_sync(0xffffffffu, gi, nn * 2);
        *(float4*)&sm_f[w][nn][q * 4] =
            *(const float4*)&feats[((size_t)b * P_ + gin) * CIN + q * 4];
    }

    // MLP (all lanes; 16 outputs each)
    const float rx = points[((size_t)b * P_ + gi) * 3 + 0] - keys[g * 3 + 0];
    const float ry = points[((size_t)b * P_ + gi) * 3 + 1] - keys[g * 3 + 1];
    const float rz = points[((size_t)b * P_ + gi) * 3 + 2] - keys[g * 3 + 2];

    float h1[16];
#pragma unroll
    for (int j = 0; j < 16; ++j) {
        const int jj = jb + j;
        h1[j] = fmaxf(fmaf(rx, sw0[0][jj], fmaf(ry, sw0[1][jj],
                      fmaf(rz, sw0[2][jj], sb0[jj]))), 0.0f);
    }
    float h1o[16];
#pragma unroll
    for (int j = 0; j < 16; ++j) h1o[j] = __shfl_xor_sync(0xffffffffu, h1[j], 1);

    float h2[16];
#pragma unroll
    for (int j = 0; j < 16; ++j) {
        const int jj = jb + j;
        float a = sb1[jj];
        const float4* wo = (const float4*)(sw1t[jj] + jb);          // own half
        const float4* wp = (const float4*)(sw1t[jj] + (jb ^ 16));   // partner half
#pragma unroll
        for (int q = 0; q < 4; ++q) {
            float4 v = wo[q];
            a = fmaf(h1[4 * q + 0], v.x, a);
            a = fmaf(h1[4 * q + 1], v.y, a);
            a = fmaf(h1[4 * q + 2], v.z, a);
            a = fmaf(h1[4 * q + 3], v.w, a);
            float4 u = wp[q];
            a = fmaf(h1o[4 * q + 0], u.x, a);
            a = fmaf(h1o[4 * q + 1], u.y, a);
            a = fmaf(h1o[4 * q + 2], u.z, a);
            a = fmaf(h1o[4 * q + 3], u.w, a);
        }
        h2[j] = fmaxf(a, 0.0f);
    }
    float h2o[16];
#pragma unroll
    for (int j = 0; j < 16; ++j) h2o[j] = __shfl_xor_sync(0xffffffffu, h2[j], 1);

#pragma unroll
    for (int j = 0; j < 16; ++j) {
        const int jj = jb + j;
        float a = sb2[jj];
        const float4* wo = (const float4*)(sw2t[jj] + jb);
        const float4* wp = (const float4*)(sw2t[jj] + (jb ^ 16));
#pragma unroll
        for (int q = 0; q < 4; ++q) {
            float4 v = wo[q];
            a = fmaf(h2[4 * q + 0], v.x, a);
            a = fmaf(h2[4 * q + 1], v.y, a);
            a = fmaf(h2[4 * q + 2], v.z, a);
            a = fmaf(h2[4 * q + 3], v.w, a);
            float4 u = wp[q];
            a = fmaf(h2o[4 * q + 0], u.x, a);
            a = fmaf(h2o[4 * q + 1], u.y, a);
            a = fmaf(h2o[4 * q + 2], u.z, a);
            a = fmaf(h2o[4 * q + 3], u.w, a);
        }
        sm_m[w][n][jj] = a;   // linear output, no relu
    }
    __syncwarp();

    // Aggregation: e[mc][c] = sum_n m[n][mc] * f[n][c]; lane owns c = 2*lane, 2*lane+1.
    float e0[32], e1[32];
#pragma unroll
    for (int j = 0; j < 32; ++j) { e0[j] = 0.0f; e1[j] = 0.0f; }

#pragma unroll
    for (int nn = 0; nn < NB; ++nn) {
        const float2 f = *(const float2*)&sm_f[w][nn][2 * lane];
        const float4* mp = (const float4*)sm_m[w][nn];
#pragma unroll
        for (int q = 0; q < 8; ++q) {
            float4 mv = mp[q];
            e0[4 * q + 0] = fmaf(mv.x, f.x, e0[4 * q + 0]);
            e1[4 * q + 0] = fmaf(mv.x, f.y, e1[4 * q + 0]);
            e0[4 * q + 1] = fmaf(mv.y, f.x, e0[4 * q + 1]);
            e1[4 * q + 1] = fmaf(mv.y, f.y, e1[4 * q + 1]);
            e0[4 * q + 2] = fmaf(mv.z, f.x, e0[4 * q + 2]);
            e1[4 * q + 2] = fmaf(mv.z, f.y, e1[4 * q + 2]);
            e0[4 * q + 3] = fmaf(mv.w, f.x, e0[4 * q + 3]);
            e1[4 * q + 3] = fmaf(mv.w, f.y, e1[4 * q + 3]);
        }
    }

    uint32_t* EhP = (uint32_t*)(g_Ehi + (size_t)g * EDIM);
    uint32_t* ElP = (uint32_t*)(g_Elo + (size_t)g * EDIM);
#pragma unroll
    for (int mc = 0; mc < 32; ++mc) {
        uint32_t lo;
        uint32_t hi = pack_split(e0[mc], e1[mc], lo);
        EhP[mc * 32 + lane] = hi;
        ElP[mc * 32 + lane] = lo;
    }
}

// ---------------------------------------------------------------------------
// Kernel 3: gemm1 HMMA — H = relu(E @ W0 + b0), 3-term bf16 split, 128x128,
// BK=64, **3-stage** cp.async pipeline (one __syncthreads per iter; the stage
// consumed at iter it was issued at it-2, so the wait is latency-free).
// Epilogue emits H as packed bf16 hi/lo.
// ---------------------------------------------------------------------------
constexpr int G1_STAGE  = 4 * 16384;          // Ahi, Alo, Bhi, Blo (64KB)
constexpr int G1_STAGES = 3;
constexpr int G1_SMEM   = G1_STAGES * G1_STAGE;   // 196608
constexpr int G1_NI     = EDIM / 64;          // 32

__global__ void __launch_bounds__(256, 1) gemm1_mma_kernel(const float* __restrict__ bias)
{
    extern __shared__ char smem[];
    const uint32_t base = smem_u32(smem);
    const int tid  = threadIdx.x;
    const int wid  = tid >> 5;
    const int lane = tid & 31;
    const int m0 = blockIdx.y * 128;
    const int n0 = blockIdx.x * 128;
    const int warpM = (wid & 1) * 64;
    const int warpN = (wid >> 1) * 32;

    const __nv_bfloat16* srcA_hi = g_Ehi + (size_t)m0 * EDIM;
    const __nv_bfloat16* srcA_lo = g_Elo + (size_t)m0 * EDIM;
    const __nv_bfloat16* srcB_hi = g_Whi + (size_t)n0 * EDIM;
    const __nv_bfloat16* srcB_lo = g_Wlo + (size_t)n0 * EDIM;

    auto load_stage = [&](int it, int slot) {
        const uint32_t sb = base + slot * G1_STAGE;
        const int k0 = it * 64;
        const __nv_bfloat16* srcs[4] = {srcA_hi, srcA_lo, srcB_hi, srcB_lo};
#pragma unroll
        for (int sub = 0; sub < 4; ++sub) {
            const __nv_bfloat16* sp = srcs[sub] + k0;
            const uint32_t sbase = sb + sub * 16384;
#pragma unroll
            for (int j = 0; j < 4; ++j) {
                const int idx = tid + j * 256;
                const int r = idx >> 3, c = idx & 7;
                const uint32_t off = (uint32_t)idx * 16;
                const uint32_t dst = sbase + (off ^ ((off >> 3) & 0x70));
                cp_async16(dst, sp + (size_t)r * EDIM + c * 8);
            }
        }
    };

    float acc[4][4][4];
#pragma unroll
    for (int i = 0; i < 4; ++i)
#pragma unroll
        for (int j = 0; j < 4; ++j)
#pragma unroll
            for (int q = 0; q < 4; ++q) acc[i][j][q] = 0.0f;

    const int aRow = ((lane >> 3) & 1) * 8 + (lane & 7);
    const int aKof = (lane >> 4) * 8;
    const int bRow = ((lane >> 4) & 1) * 8 + (lane & 7);
    const int bKof = ((lane >> 3) & 1) * 8;

    load_stage(0, 0);
    cp_commit();
    load_stage(1, 1);
    cp_commit();

    int cslot = 0;   // slot holding stage `it`
    int lslot = 2;   // slot to load stage `it+2` into

    for (int it = 0; it < G1_NI; ++it) {
        if (it == G1_NI - 1) cp_wait<0>(); else cp_wait<1>();
        __syncthreads();   // all warps past compute(it-1); slot lslot reusable

        if (it + 2 < G1_NI) {
            load_stage(it + 2, lslot);
            cp_commit();
            if (++lslot == G1_STAGES) lslot = 0;
        }

        const uint32_t sb = base + cslot * G1_STAGE;
        if (++cslot == G1_STAGES) cslot = 0;
        const uint32_t sA_hi = sb;
        const uint32_t sA_lo = sb + 16384;
        const uint32_t sB_hi = sb + 32768;
        const uint32_t sB_lo = sb + 49152;

#pragma unroll
        for (int kk = 0; kk < 4; ++kk) {
            const int k0 = kk * 16;
            uint32_t ah[4][4], al[4][4], bh[2][4], bl[2][4];
#pragma unroll
            for (int mi = 0; mi < 4; ++mi) {
                const int row = warpM + mi * 16 + aRow;
                const int col = k0 + aKof;
                const uint32_t off = (uint32_t)(row * 128 + col * 2);
                const uint32_t sw  = off ^ ((off >> 3) & 0x70);
                ldm_x4(ah[mi], sA_hi + sw);
                ldm_x4(al[mi], sA_lo + sw);
            }
#pragma unroll
            for (int nj = 0; nj < 2; ++nj) {
                const int row = warpN + nj * 16 + bRow;
                const int col = k0 + bKof;
                const uint32_t off = (uint32_t)(row * 128 + col * 2);
                const uint32_t sw  = off ^ ((off >> 3) & 0x70);
                ldm_x4(bh[nj], sB_hi + sw);
                ldm_x4(bl[nj], sB_lo + sw);
            }
#pragma unroll
            for (int mi = 0; mi < 4; ++mi)
#pragma unroll
                for (int nj = 0; nj < 2; ++nj)
#pragma unroll
                    for (int nk = 0; nk < 2; ++nk) {
                        float* d = acc[mi][nj * 2 + nk];
                        mma_bf16(d, ah[mi], bh[nj][nk * 2], bh[nj][nk * 2 + 1]);
                        mma_bf16(d, ah[mi], bl[nj][nk * 2], bl[nj][nk * 2 + 1]);
                        mma_bf16(d, al[mi], bh[nj][nk * 2], bh[nj][nk * 2 + 1]);
                    }
        }
    }

    // Epilogue: bias + relu, split to bf16 hi/lo, packed u32 stores.
#pragma unroll
    for (int mi = 0; mi < 4; ++mi) {
        const int row = m0 + warpM + mi * 16 + (lane >> 2);
#pragma unroll
        for (int ni = 0; ni < 4; ++ni) {
            const int col = n0 + warpN + ni * 8 + 2 * (lane & 3);
            const float b0v = bias[col], b1v = bias[col + 1];
            const float v0 = fmaxf(acc[mi][ni][0] + b0v, 0.0f);
            const float v1 = fmaxf(acc[mi][ni][1] + b1v, 0.0f);
            const float v2 = fmaxf(acc[mi][ni][2] + b0v, 0.0f);
            const float v3 = fmaxf(acc[mi][ni][3] + b1v, 0.0f);
            uint32_t lo01, lo23;
            const uint32_t hi01 = pack_split(v0, v1, lo01);
            const uint32_t hi23 = pack_split(v2, v3, lo23);
            ((uint32_t*)(g_Hhi + (size_t)row * FH))[col >> 1]       = hi01;
            ((uint32_t*)(g_Hlo + (size_t)row * FH))[col >> 1]       = lo01;
            ((uint32_t*)(g_Hhi + (size_t)(row + 8) * FH))[col >> 1] = hi23;
            ((uint32_t*)(g_Hlo + (size_t)(row + 8) * FH))[col >> 1] = lo23;
        }
    }
}

// ---------------------------------------------------------------------------
// Kernel 4: gemm2 HMMA — out = H @ W1 + b1, 3-term bf16 split. (unchanged)
// ---------------------------------------------------------------------------
constexpr int G2_A_BYTES = 64 * 64 * 2;        // 8192
constexpr int G2_B_BYTES = 128 * 64 * 2;       // 16384
constexpr int G2_STAGE   = 2 * G2_A_BYTES + 2 * G2_B_BYTES;   // 49152
constexpr int G2_SMEM    = 2 * G2_STAGE;       // 98304
constexpr int G2_NI      = FH / 64;            // 4

__global__ void __launch_bounds__(256, 1) gemm2_mma_kernel(const float* __restrict__ bias,
                                                           float* __restrict__ C)
{
    extern __shared__ char smem[];
    const uint32_t base = smem_u32(smem);
    const int tid  = threadIdx.x;
    const int wid  = tid >> 5;
    const int lane = tid & 31;
    const int m0 = blockIdx.y * 64;
    const int warpM = (wid & 1) * 32;
    const int warpN = (wid >> 1) * 32;

    const __nv_bfloat16* srcA_hi = g_Hhi + (size_t)m0 * FH;
    const __nv_bfloat16* srcA_lo = g_Hlo + (size_t)m0 * FH;

    auto load_stage = [&](int it) {
        const uint32_t sb = base + (it & 1) * G2_STAGE;
        const int k0 = it * 64;
#pragma unroll
        for (int s = 0; s < 2; ++s) {
            const __nv_bfloat16* sp = (s == 0 ? srcA_hi : srcA_lo) + k0;
            const uint32_t sbase = sb + s * G2_A_BYTES;
#pragma unroll
            for (int j = 0; j < 2; ++j) {
                const int idx = tid + j * 256;              // 0..511
                const int r = idx >> 3, c = idx & 7;
                const uint32_t off = (uint32_t)idx * 16;
                const uint32_t dst = sbase + (off ^ ((off >> 3) & 0x70));
                cp_async16(dst, sp + (size_t)r * FH + c * 8);
            }
        }
#pragma unroll
        for (int s = 0; s < 2; ++s) {
            const __nv_bfloat16* sp = (s == 0 ? g_W1hi : g_W1lo) + k0;
            const uint32_t sbase = sb + 2 * G2_A_BYTES + s * G2_B_BYTES;
#pragma unroll
            for (int j = 0; j < 4; ++j) {
                const int idx = tid + j * 256;              // 0..1023
                const int r = idx >> 3, c = idx & 7;
                const uint32_t off = (uint32_t)idx * 16;
                const uint32_t dst = sbase + (off ^ ((off >> 3) & 0x70));
                cp_async16(dst, sp + (size_t)r * FH + c * 8);
            }
        }
    };

    float acc[2][4][4];
#pragma unroll
    for (int i = 0; i < 2; ++i)
#pragma unroll
        for (int j = 0; j < 4; ++j)
#pragma unroll
            for (int q = 0; q < 4; ++q) acc[i][j][q] = 0.0f;

    const int aRow = ((lane >> 3) & 1) * 8 + (lane & 7);
    const int aKof = (lane >> 4) * 8;
    const int bRow = ((lane >> 4) & 1) * 8 + (lane & 7);
    const int bKof = ((lane >> 3) & 1) * 8;

    load_stage(0);
    cp_commit();

    for (int it = 0; it < G2_NI; ++it) {
        if (it + 1 < G2_NI) {
            load_stage(it + 1);
            cp_commit();
            cp_wait<1>();
        } else {
            cp_wait<0>();
        }
        __syncthreads();

        const uint32_t sb = base + (it & 1) * G2_STAGE;
        const uint32_t sA_hi = sb;
        const uint32_t sA_lo = sb + G2_A_BYTES;
        const uint32_t sB_hi = sb + 2 * G2_A_BYTES;
        const uint32_t sB_lo = sb + 2 * G2_A_BYTES + G2_B_BYTES;

#pragma unroll
        for (int kk = 0; kk < 4; ++kk) {
            const int k0 = kk * 16;
            uint32_t ah[2][4], al[2][4], bh[2][4], bl[2][4];
#pragma unroll
            for (int mi = 0; mi < 2; ++mi) {
                const int row = warpM + mi * 16 + aRow;
                const int col = k0 + aKof;
                const uint32_t off = (uint32_t)(row * 128 + col * 2);
                const uint32_t sw  = off ^ ((off >> 3) & 0x70);
                ldm_x4(ah[mi], sA_hi + sw);
                ldm_x4(al[mi], sA_lo + sw);
            }
#pragma unroll
            for (int nj = 0; nj < 2; ++nj) {
                const int row = warpN + nj * 16 + bRow;
                const int col = k0 + bKof;
                const uint32_t off = (uint32_t)(row * 128 + col * 2);
                const uint32_t sw  = off ^ ((off >> 3) & 0x70);
                ldm_x4(bh[nj], sB_hi + sw);
                ldm_x4(bl[nj], sB_lo + sw);
            }
#pragma unroll
            for (int mi = 0; mi < 2; ++mi)
#pragma unroll
                for (int nj = 0; nj < 2; ++nj)
#pragma unroll
                    for (int nk = 0; nk < 2; ++nk) {
                        float* d = acc[mi][nj * 2 + nk];
                        mma_bf16(d, ah[mi], bh[nj][nk * 2], bh[nj][nk * 2 + 1]);
                        mma_bf16(d, ah[mi], bl[nj][nk * 2], bl[nj][nk * 2 + 1]);
                        mma_bf16(d, al[mi], bh[nj][nk * 2], bh[nj][nk * 2 + 1]);
                    }
        }
        __syncthreads();
    }

    // Epilogue: bias, fp32 out (no relu)
#pragma unroll
    for (int mi = 0; mi < 2; ++mi) {
        const int row = m0 + warpM + mi * 16 + (lane >> 2);
#pragma unroll
        for (int ni = 0; ni < 4; ++ni) {
            const int col = warpN + ni * 8 + 2 * (lane & 3);
            const float b0v = bias[col], b1v = bias[col + 1];
            float2 v0, v1;
            v0.x = acc[mi][ni][0] + b0v;
            v0.y = acc[mi][ni][1] + b1v;
            v1.x = acc[mi][ni][2] + b0v;
            v1.y = acc[mi][ni][3] + b1v;
            *(float2*)&C[(size_t)row * COUT + col]       = v0;
            *(float2*)&C[(size_t)(row + 8) * COUT + col] = v1;
        }
    }
}

// ---------------------------------------------------------------------------
extern "C" void kernel_launch(void* const* d_in, const int* in_sizes, int n_in,
                              void* d_out, int out_size)
{
    const float* keys   = (const float*)d_in[0];
    const float* points = (const float*)d_in[1];
    const float* feats  = (const float*)d_in[2];
    const float* wc0W   = (const float*)d_in[3];
    const float* wc0b   = (const float*)d_in[4];
    const float* wc1W   = (const float*)d_in[5];
    const float* wc1b   = (const float*)d_in[6];
    const float* wc2W   = (const float*)d_in[7];
    const float* wc2b   = (const float*)d_in[8];
    const float* fc0W   = (const float*)d_in[9];
    const float* fc0b   = (const float*)d_in[10];
    const float* fc1W   = (const float*)d_in[11];
    const float* fc1b   = (const float*)d_in[12];
    float* out = (float*)d_out;

    cudaFuncSetAttribute(gemm1_mma_kernel,
                         cudaFuncAttributeMaxDynamicSharedMemorySize, G1_SMEM);
    cudaFuncSetAttribute(gemm2_mma_kernel,
                         cudaFuncAttributeMaxDynamicSharedMemorySize, G2_SMEM);

    knn_prep_kernel<<<640 + GK / 8, 256>>>(keys, points, fc0W, fc1W);
    edge_kernel<<<GK / 4, 128>>>(keys, points, feats,
                                 wc0W, wc0b, wc1W, wc1b, wc2W, wc2b);
    gemm1_mma_kernel<<<dim3(FH / 128, GK / 128), 256, G1_SMEM>>>(fc0b);
    gemm2_mma_kernel<<<dim3(1, GK / 64), 256, G2_SMEM>>>(fc1b, out);
}